// round 8
// baseline (speedup 1.0000x reference)
#include <cuda_runtime.h>
#include <math.h>
#include <stdint.h>

#define BATCH 4
#define CH    128
#define HH    128
#define WW    128
#define HWQ   16384
#define NHEAD 8
#define NPNT  8
#define NOFF  128
#define NATT  64
#define MAXRES 10.0f

#define LDA 132        // k-major A tile stride (floats), 128+4 pad
#define LDB128 132
#define LDB192 196

// ---- scratch ----
__device__ float  d_val [(size_t)BATCH * HWQ * CH];
__device__ float  d_agg [(size_t)BATCH * HWQ * CH];
__device__ float2 d_loc [(size_t)BATCH * HWQ * NATT];
__device__ float  d_attn[(size_t)BATCH * HWQ * NATT];

// ============================================================================
// helpers
// ============================================================================
__device__ __forceinline__ void mma_tf32(float* c, uint32_t a0, uint32_t a1,
                                         uint32_t a2, uint32_t a3,
                                         uint32_t b0, uint32_t b1) {
    asm volatile(
        "mma.sync.aligned.m16n8k8.row.col.f32.tf32.tf32.f32 "
        "{%0,%1,%2,%3},{%4,%5,%6,%7},{%8,%9},{%0,%1,%2,%3};"
        : "+f"(c[0]), "+f"(c[1]), "+f"(c[2]), "+f"(c[3])
        : "r"(a0), "r"(a1), "r"(a2), "r"(a3), "r"(b0), "r"(b1));
}

__device__ __forceinline__ void split2(float v, float& h, float& l) {
    h = __uint_as_float(__float_as_uint(v) & 0xFFFFE000u);
    l = v - h;
}

__device__ __forceinline__ float tf32_rna(float f) {
    uint32_t r;
    asm("cvt.rna.tf32.f32 %0, %1;" : "=r"(r) : "f"(f));
    return __uint_as_float(r);
}

__device__ __forceinline__ uint32_t fb(float f) { return __float_as_uint(f); }

// ============================================================================
// Kernel 1: ext @ [W_off|W_attn]  (M=128/block, N=192, K=128)
// tf32 3-pass split (AhBh + AlBh + AhBl) ~ fp32 accuracy — precision-critical
// (drives sample positions + softmax). 8 warps: mw = w&3, nw = w>>2.
// ============================================================================
__global__ __launch_bounds__(256) void k1_offattn(
    const float* __restrict__ ext, const float* __restrict__ flow,
    const float* __restrict__ W_off, const float* __restrict__ b_off,
    const float* __restrict__ W_attn, const float* __restrict__ b_attn)
{
    extern __shared__ float sm[];
    float* AH = sm;                    // 32*132
    float* AL = AH + 32*LDA;
    float* BH = AL + 32*LDA;           // 32*196
    float* BL = BH + 32*LDB192;

    const int tid  = threadIdx.x;
    const int lane = tid & 31;
    const int warp = tid >> 5;
    const int mw   = warp & 3;
    const int nw   = warp >> 2;
    const int g    = lane >> 2;
    const int tq   = lane & 3;
    const int row0 = blockIdx.x * 128;
    const int b    = row0 / HWQ;
    const int q0   = row0 % HWQ;

    float acc[2][12][4];
#pragma unroll
    for (int t = 0; t < 2; ++t)
#pragma unroll
        for (int j = 0; j < 12; ++j)
#pragma unroll
            for (int v = 0; v < 4; ++v) acc[t][j][v] = 0.f;

    for (int kc = 0; kc < 4; ++kc) {
        // ---- stage A (ext is (C, HWQ): k rows, m contiguous) ----
        {
            const int m4 = (tid & 31) * 4;
            const int kb = tid >> 5;
            const float* src = ext + ((size_t)b*CH + kc*32)*HWQ + q0;
#pragma unroll
            for (int it = 0; it < 4; ++it) {
                int k = kb + it*8;
                float4 v = __ldg((const float4*)(src + (size_t)k*HWQ + m4));
                float4 h, l;
                split2(v.x, h.x, l.x); split2(v.y, h.y, l.y);
                split2(v.z, h.z, l.z); split2(v.w, h.w, l.w);
                *(float4*)(AH + k*LDA + m4) = h;
                *(float4*)(AL + k*LDA + m4) = l;
            }
        }
        // ---- stage B = [W_off | W_attn], k-major, 192 cols, split hi/lo ----
#pragma unroll
        for (int it = 0; it < 6; ++it) {
            int idx = tid + it*256;            // < 1536
            int k = idx / 48, f4 = idx % 48;
            const float* srcp = (f4 < 32)
                ? W_off  + (size_t)(kc*32 + k)*NOFF + f4*4
                : W_attn + (size_t)(kc*32 + k)*NATT + (f4-32)*4;
            float4 v = __ldg((const float4*)srcp);
            float4 h, l;
            split2(v.x, h.x, l.x); split2(v.y, h.y, l.y);
            split2(v.z, h.z, l.z); split2(v.w, h.w, l.w);
            *(float4*)(BH + k*LDB192 + f4*4) = h;
            *(float4*)(BL + k*LDB192 + f4*4) = l;
        }
        __syncthreads();

#pragma unroll
        for (int k8 = 0; k8 < 4; ++k8) {
            const int kr = k8*8 + tq;
            uint32_t ah[2][4], al[2][4];
#pragma unroll
            for (int t = 0; t < 2; ++t) {
                int m = mw*32 + t*16 + g;
                ah[t][0] = fb(AH[kr*LDA + m]);     ah[t][1] = fb(AH[kr*LDA + m + 8]);
                ah[t][2] = fb(AH[(kr+4)*LDA + m]); ah[t][3] = fb(AH[(kr+4)*LDA + m + 8]);
                al[t][0] = fb(AL[kr*LDA + m]);     al[t][1] = fb(AL[kr*LDA + m + 8]);
                al[t][2] = fb(AL[(kr+4)*LDA + m]); al[t][3] = fb(AL[(kr+4)*LDA + m + 8]);
            }
            uint32_t bh[12][2], bl[12][2];
#pragma unroll
            for (int j = 0; j < 12; ++j) {
                int n = nw*96 + j*8 + g;
                bh[j][0] = fb(BH[kr*LDB192 + n]); bh[j][1] = fb(BH[(kr+4)*LDB192 + n]);
                bl[j][0] = fb(BL[kr*LDB192 + n]); bl[j][1] = fb(BL[(kr+4)*LDB192 + n]);
            }
#pragma unroll
            for (int t = 0; t < 2; ++t)
#pragma unroll
                for (int j = 0; j < 12; ++j) {
                    mma_tf32(acc[t][j], ah[t][0],ah[t][1],ah[t][2],ah[t][3], bh[j][0],bh[j][1]);
                    mma_tf32(acc[t][j], al[t][0],al[t][1],al[t][2],al[t][3], bh[j][0],bh[j][1]);
                    mma_tf32(acc[t][j], ah[t][0],ah[t][1],ah[t][2],ah[t][3], bl[j][0],bl[j][1]);
                }
        }
        __syncthreads();
    }

    // ---- epilogue: rows held by this thread ----
    int   qrow[4]; float fxv[4], fyv[4]; float wiv[4], hiv[4];
#pragma unroll
    for (int t = 0; t < 2; ++t)
#pragma unroll
        for (int rr = 0; rr < 2; ++rr) {
            int r  = mw*32 + t*16 + g + rr*8;
            int qq = q0 + r;
            int ri = t*2 + rr;
            qrow[ri] = qq;
            fxv[ri] = __ldg(&flow[(size_t)b*2*HWQ + qq]);
            fyv[ri] = __ldg(&flow[(size_t)b*2*HWQ + HWQ + qq]);
            wiv[ri] = (float)(qq & (WW-1));
            hiv[ri] = (float)((qq >> 7) & (HH-1));
        }

#pragma unroll
    for (int j = 0; j < 12; ++j) {
        int c = nw*96 + j*8 + 2*tq;     // warp-uniform branch boundary (per j)
        if (c < NOFF) {
            int n = c >> 1;
            float b0v = __ldg(&b_off[c]), b1v = __ldg(&b_off[c+1]);
#pragma unroll
            for (int t = 0; t < 2; ++t)
#pragma unroll
                for (int rr = 0; rr < 2; ++rr) {
                    int ri = t*2 + rr;
                    float ox = MAXRES * tanhf(acc[t][j][rr*2]   + b0v);
                    float oy = MAXRES * tanhf(acc[t][j][rr*2+1] + b1v);
                    float lx = (wiv[ri] + 0.5f + fxv[ri] + ox) * (1.f/WW);
                    float ly = (hiv[ri] + 0.5f + fyv[ri] + oy) * (1.f/HH);
                    d_loc[((size_t)b*HWQ + qrow[ri])*NATT + n] = make_float2(lx, ly);
                }
        } else {
            int ca = c - NOFF;
            float ba0 = __ldg(&b_attn[ca]), ba1 = __ldg(&b_attn[ca+1]);
#pragma unroll
            for (int t = 0; t < 2; ++t)
#pragma unroll
                for (int rr = 0; rr < 2; ++rr) {
                    float v0 = acc[t][j][rr*2]   + ba0;
                    float v1 = acc[t][j][rr*2+1] + ba1;
                    float mx = fmaxf(v0, v1);
                    mx = fmaxf(mx, __shfl_xor_sync(0xffffffffu, mx, 1));
                    mx = fmaxf(mx, __shfl_xor_sync(0xffffffffu, mx, 2));
                    float e0 = __expf(v0 - mx), e1 = __expf(v1 - mx);
                    float s = e0 + e1;
                    s += __shfl_xor_sync(0xffffffffu, s, 1);
                    s += __shfl_xor_sync(0xffffffffu, s, 2);
                    float inv = 1.f / s;
                    *(float2*)&d_attn[((size_t)b*HWQ + qrow[t*2+rr])*NATT + ca] =
                        make_float2(e0*inv, e1*inv);
                }
        }
    }
}

// ============================================================================
// Kernel 2: val = nbr @ W_val + b_val  (N=128), tf32 2-pass (A split, B rna)
// ============================================================================
__global__ __launch_bounds__(256) void k_val(
    const float* __restrict__ nbr,
    const float* __restrict__ W_val, const float* __restrict__ b_val)
{
    extern __shared__ float sm[];
    float* AH = sm;
    float* AL = AH + 32*LDA;
    float* BS = AL + 32*LDA;

    const int tid  = threadIdx.x;
    const int lane = tid & 31;
    const int warp = tid >> 5;
    const int mw   = warp & 3;
    const int nw   = warp >> 2;
    const int g    = lane >> 2;
    const int tq   = lane & 3;
    const int row0 = blockIdx.x * 128;
    const int b    = row0 / HWQ;
    const int q0   = row0 % HWQ;

    float acc[2][8][4];
#pragma unroll
    for (int t = 0; t < 2; ++t)
#pragma unroll
        for (int j = 0; j < 8; ++j)
#pragma unroll
            for (int v = 0; v < 4; ++v) acc[t][j][v] = 0.f;

    for (int kc = 0; kc < 4; ++kc) {
        {
            const int m4 = (tid & 31) * 4;
            const int kb = tid >> 5;
            const float* src = nbr + ((size_t)b*CH + kc*32)*HWQ + q0;
#pragma unroll
            for (int it = 0; it < 4; ++it) {
                int k = kb + it*8;
                float4 v = __ldg((const float4*)(src + (size_t)k*HWQ + m4));
                float4 h, l;
                split2(v.x, h.x, l.x); split2(v.y, h.y, l.y);
                split2(v.z, h.z, l.z); split2(v.w, h.w, l.w);
                *(float4*)(AH + k*LDA + m4) = h;
                *(float4*)(AL + k*LDA + m4) = l;
            }
        }
#pragma unroll
        for (int it = 0; it < 4; ++it) {
            int idx = tid + it*256;
            int k = idx >> 5, f4 = idx & 31;
            float4 v = __ldg((const float4*)(W_val + (size_t)(kc*32 + k)*CH + f4*4));
            v.x = tf32_rna(v.x); v.y = tf32_rna(v.y);
            v.z = tf32_rna(v.z); v.w = tf32_rna(v.w);
            *(float4*)(BS + k*LDB128 + f4*4) = v;
        }
        __syncthreads();

#pragma unroll
        for (int k8 = 0; k8 < 4; ++k8) {
            const int kr = k8*8 + tq;
            uint32_t ah[2][4], al[2][4];
#pragma unroll
            for (int t = 0; t < 2; ++t) {
                int m = mw*32 + t*16 + g;
                ah[t][0] = fb(AH[kr*LDA + m]);     ah[t][1] = fb(AH[kr*LDA + m + 8]);
                ah[t][2] = fb(AH[(kr+4)*LDA + m]); ah[t][3] = fb(AH[(kr+4)*LDA + m + 8]);
                al[t][0] = fb(AL[kr*LDA + m]);     al[t][1] = fb(AL[kr*LDA + m + 8]);
                al[t][2] = fb(AL[(kr+4)*LDA + m]); al[t][3] = fb(AL[(kr+4)*LDA + m + 8]);
            }
            uint32_t bs[8][2];
#pragma unroll
            for (int j = 0; j < 8; ++j) {
                int n = nw*64 + j*8 + g;
                bs[j][0] = fb(BS[kr*LDB128 + n]); bs[j][1] = fb(BS[(kr+4)*LDB128 + n]);
            }
#pragma unroll
            for (int t = 0; t < 2; ++t)
#pragma unroll
                for (int j = 0; j < 8; ++j) {
                    mma_tf32(acc[t][j], ah[t][0],ah[t][1],ah[t][2],ah[t][3], bs[j][0],bs[j][1]);
                    mma_tf32(acc[t][j], al[t][0],al[t][1],al[t][2],al[t][3], bs[j][0],bs[j][1]);
                }
        }
        __syncthreads();
    }

#pragma unroll
    for (int j = 0; j < 8; ++j) {
        int c = nw*64 + j*8 + 2*tq;
        float b0v = __ldg(&b_val[c]), b1v = __ldg(&b_val[c+1]);
#pragma unroll
        for (int t = 0; t < 2; ++t)
#pragma unroll
            for (int rr = 0; rr < 2; ++rr) {
                int r = row0 + mw*32 + t*16 + g + rr*8;
                *(float2*)&d_val[(size_t)r*CH + c] =
                    make_float2(acc[t][j][rr*2] + b0v, acc[t][j][rr*2+1] + b1v);
            }
    }
}

// ============================================================================
// Kernel 3: bilinear gather + attention aggregation.
// Block = 16 q in an 8x2 spatial tile (x-major), 512 threads.
// Spatial tiling -> bilinear corners of adjacent q alias the same d_val rows
// in both x and y => higher L1 hit rate on the gather traffic.
// ============================================================================
__global__ __launch_bounds__(512) void k_gather()
{
    __shared__ float2 loc_s[16][NATT];
    __shared__ float  attn_s[16][NATT];
    const int tx = threadIdx.x;
    const int tile = blockIdx.x;              // 0 .. 4*1024-1
    const int img  = tile >> 10;              // batch
    const int tin  = tile & 1023;
    const int ty0  = (tin >> 4) * 2;
    const int tx0  = (tin & 15) * 8;

    for (int i = tx; i < 1024; i += 512) {
        int tq = i >> 6, n = i & 63;
        int ly = tq >> 3, lx = tq & 7;
        size_t row = (size_t)img*HWQ + (size_t)(ty0 + ly)*WW + tx0 + lx;
        loc_s[tq][n]  = d_loc [row*NATT + n];
        attn_s[tq][n] = d_attn[row*NATT + n];
    }
    __syncthreads();

    const int tq  = tx >> 5;                  // 0..15
    const int c4  = tx & 31;                  // float4 channel group
    const int h   = c4 >> 2;
    const int ly  = tq >> 3, lx = tq & 7;
    const size_t row = (size_t)img*HWQ + (size_t)(ty0 + ly)*WW + tx0 + lx;
    const float* vb = d_val + (size_t)img * HWQ * CH;

    float4 acc = make_float4(0.f, 0.f, 0.f, 0.f);
#pragma unroll
    for (int p = 0; p < NPNT; ++p) {
        int n = h*NPNT + p;
        float2 l = loc_s[tq][n];
        float  a = attn_s[tq][n];
        float x = l.x * (float)WW - 0.5f;
        float y = l.y * (float)HH - 0.5f;
        float x0f = floorf(x), y0f = floorf(y);
        float wx = x - x0f,    wy = y - y0f;
        int x0 = (int)x0f, y0 = (int)y0f;
        int x1 = x0 + 1,   y1 = y0 + 1;
        bool xv0 = (x0 >= 0) & (x0 < WW);
        bool xv1 = (x1 >= 0) & (x1 < WW);
        bool yv0 = (y0 >= 0) & (y0 < HH);
        bool yv1 = (y1 >= 0) & (y1 < HH);
        float w00 = (1.f-wx)*(1.f-wy) * a;
        float w10 = wx*(1.f-wy) * a;
        float w01 = (1.f-wx)*wy * a;
        float w11 = wx*wy * a;
        if (xv0 & yv0) { float4 gg = __ldg((const float4*)(vb + (size_t)(y0*WW + x0)*CH) + c4);
            acc.x=fmaf(w00,gg.x,acc.x); acc.y=fmaf(w00,gg.y,acc.y); acc.z=fmaf(w00,gg.z,acc.z); acc.w=fmaf(w00,gg.w,acc.w); }
        if (xv1 & yv0) { float4 gg = __ldg((const float4*)(vb + (size_t)(y0*WW + x1)*CH) + c4);
            acc.x=fmaf(w10,gg.x,acc.x); acc.y=fmaf(w10,gg.y,acc.y); acc.z=fmaf(w10,gg.z,acc.z); acc.w=fmaf(w10,gg.w,acc.w); }
        if (xv0 & yv1) { float4 gg = __ldg((const float4*)(vb + (size_t)(y1*WW + x0)*CH) + c4);
            acc.x=fmaf(w01,gg.x,acc.x); acc.y=fmaf(w01,gg.y,acc.y); acc.z=fmaf(w01,gg.z,acc.z); acc.w=fmaf(w01,gg.w,acc.w); }
        if (xv1 & yv1) { float4 gg = __ldg((const float4*)(vb + (size_t)(y1*WW + x1)*CH) + c4);
            acc.x=fmaf(w11,gg.x,acc.x); acc.y=fmaf(w11,gg.y,acc.y); acc.z=fmaf(w11,gg.z,acc.z); acc.w=fmaf(w11,gg.w,acc.w); }
    }
    *((float4*)(d_agg + row*CH) + c4) = acc;
}

// ============================================================================
// Kernel 4: out = agg @ W_out + b_out, transposed store (N=128)
// tf32 2-pass; epilogue via 129-stride smem buffer for coalesced stores
// ============================================================================
__global__ __launch_bounds__(256) void k_out(
    const float* __restrict__ W_out, const float* __restrict__ b_out,
    float* __restrict__ out)
{
    extern __shared__ float sm[];
    float* AH = sm;
    float* AL = AH + 32*LDA;
    float* BS = AL + 32*LDA;

    const int tid  = threadIdx.x;
    const int lane = tid & 31;
    const int warp = tid >> 5;
    const int mw   = warp & 3;
    const int nw   = warp >> 2;
    const int g    = lane >> 2;
    const int tq   = lane & 3;
    const int row0 = blockIdx.x * 128;
    const int b    = row0 / HWQ;
    const int q0   = row0 % HWQ;

    float acc[2][8][4];
#pragma unroll
    for (int t = 0; t < 2; ++t)
#pragma unroll
        for (int j = 0; j < 8; ++j)
#pragma unroll
            for (int v = 0; v < 4; ++v) acc[t][j][v] = 0.f;

    for (int kc = 0; kc < 4; ++kc) {
        {
            const int m  = tid & 127;
            const int g0 = tid >> 7;
            const float* src = d_agg + (size_t)(row0 + m)*CH + kc*32;
#pragma unroll
            for (int it = 0; it < 4; ++it) {
                int gg = g0 + it*2;
                float4 v = *(const float4*)(src + gg*4);
                float h, l;
                split2(v.x, h, l); AH[(gg*4+0)*LDA + m] = h; AL[(gg*4+0)*LDA + m] = l;
                split2(v.y, h, l); AH[(gg*4+1)*LDA + m] = h; AL[(gg*4+1)*LDA + m] = l;
                split2(v.z, h, l); AH[(gg*4+2)*LDA + m] = h; AL[(gg*4+2)*LDA + m] = l;
                split2(v.w, h, l); AH[(gg*4+3)*LDA + m] = h; AL[(gg*4+3)*LDA + m] = l;
            }
        }
#pragma unroll
        for (int it = 0; it < 4; ++it) {
            int idx = tid + it*256;
            int k = idx >> 5, f4 = idx & 31;
            float4 v = __ldg((const float4*)(W_out + (size_t)(kc*32 + k)*CH + f4*4));
            v.x = tf32_rna(v.x); v.y = tf32_rna(v.y);
            v.z = tf32_rna(v.z); v.w = tf32_rna(v.w);
            *(float4*)(BS + k*LDB128 + f4*4) = v;
        }
        __syncthreads();

#pragma unroll
        for (int k8 = 0; k8 < 4; ++k8) {
            const int kr = k8*8 + tq;
            uint32_t ah[2][4], al[2][4];
#pragma unroll
            for (int t = 0; t < 2; ++t) {
                int m = mw*32 + t*16 + g;
                ah[t][0] = fb(AH[kr*LDA + m]);     ah[t][1] = fb(AH[kr*LDA + m + 8]);
                ah[t][2] = fb(AH[(kr+4)*LDA + m]); ah[t][3] = fb(AH[(kr+4)*LDA + m + 8]);
                al[t][0] = fb(AL[kr*LDA + m]);     al[t][1] = fb(AL[kr*LDA + m + 8]);
                al[t][2] = fb(AL[(kr+4)*LDA + m]); al[t][3] = fb(AL[(kr+4)*LDA + m + 8]);
            }
            uint32_t bs[8][2];
#pragma unroll
            for (int j = 0; j < 8; ++j) {
                int n = nw*64 + j*8 + g;
                bs[j][0] = fb(BS[kr*LDB128 + n]); bs[j][1] = fb(BS[(kr+4)*LDB128 + n]);
            }
#pragma unroll
            for (int t = 0; t < 2; ++t)
#pragma unroll
                for (int j = 0; j < 8; ++j) {
                    mma_tf32(acc[t][j], ah[t][0],ah[t][1],ah[t][2],ah[t][3], bs[j][0],bs[j][1]);
                    mma_tf32(acc[t][j], al[t][0],al[t][1],al[t][2],al[t][3], bs[j][0],bs[j][1]);
                }
        }
        __syncthreads();
    }

    float* buf = sm;                       // reuse; 128*129 floats
#pragma unroll
    for (int j = 0; j < 8; ++j) {
        int c = nw*64 + j*8 + 2*tq;
        float b0v = __ldg(&b_out[c]), b1v = __ldg(&b_out[c+1]);
#pragma unroll
        for (int t = 0; t < 2; ++t)
#pragma unroll
            for (int rr = 0; rr < 2; ++rr) {
                int m = mw*32 + t*16 + g + rr*8;
                buf[m*129 + c]     = acc[t][j][rr*2]   + b0v;
                buf[m*129 + c + 1] = acc[t][j][rr*2+1] + b1v;
            }
    }
    __syncthreads();
    for (int idx = tid; idx < 128*128; idx += 256) {
        int m = idx & 127, n = idx >> 7;
        out[(size_t)b*CH*HWQ + (size_t)n*HWQ + q0 + m] = buf[m*129 + n];
    }
}

// ============================================================================
extern "C" void kernel_launch(void* const* d_in, const int* in_sizes, int n_in,
                              void* d_out, int out_size)
{
    const float* nbr    = (const float*)d_in[0];
    const float* ext    = (const float*)d_in[1];
    const float* flow   = (const float*)d_in[2];
    const float* W_off  = (const float*)d_in[3];
    const float* b_off  = (const float*)d_in[4];
    const float* W_attn = (const float*)d_in[5];
    const float* b_attn = (const float*)d_in[6];
    const float* W_val  = (const float*)d_in[7];
    const float* b_val  = (const float*)d_in[8];
    const float* W_out  = (const float*)d_in[9];
    const float* b_out  = (const float*)d_in[10];
    float* out = (float*)d_out;

    const int SM_K1 = (2*32*LDA + 2*32*LDB192) * 4;              // 83968
    const int SM_KV = (2*32*LDA + 32*LDB128) * 4;                // 50688
    const int SM_KO_MMA = (2*32*LDA + 32*LDB128) * 4;
    const int SM_KO_BUF = 128*129*4;                              // 66048
    const int SM_KO = SM_KO_BUF > SM_KO_MMA ? SM_KO_BUF : SM_KO_MMA;

    cudaFuncSetAttribute(k1_offattn, cudaFuncAttributeMaxDynamicSharedMemorySize, SM_K1);
    cudaFuncSetAttribute(k_val,      cudaFuncAttributeMaxDynamicSharedMemorySize, SM_KV);
    cudaFuncSetAttribute(k_out,      cudaFuncAttributeMaxDynamicSharedMemorySize, SM_KO);

    const int nblk = BATCH * HWQ / 128;   // 512

    k1_offattn<<<nblk, 256, SM_K1>>>(ext, flow, W_off, b_off, W_attn, b_attn);
    k_val     <<<nblk, 256, SM_KV>>>(nbr, W_val, b_val);
    k_gather  <<<BATCH * HWQ / 16, 512>>>();
    k_out     <<<nblk, 256, SM_KO>>>(W_out, b_out, out);
}

// round 9
// speedup vs baseline: 1.0207x; 1.0207x over previous
#include <cuda_runtime.h>
#include <cuda_fp16.h>
#include <math.h>
#include <stdint.h>

#define BATCH 4
#define CH    128
#define HH    128
#define WW    128
#define HWQ   16384
#define NHEAD 8
#define NPNT  8
#define NOFF  128
#define NATT  64
#define MAXRES 10.0f

#define LDA 132        // k-major A tile stride (floats), 128+4 pad
#define LDB128 132
#define LDB192 196

// ---- scratch ----
__device__ __half d_val_h[(size_t)BATCH * HWQ * CH];   // fp16 value features
__device__ float  d_agg [(size_t)BATCH * HWQ * CH];
__device__ float2 d_loc [(size_t)BATCH * HWQ * NATT];
__device__ float  d_attn[(size_t)BATCH * HWQ * NATT];

// ============================================================================
// helpers
// ============================================================================
__device__ __forceinline__ void mma_tf32(float* c, uint32_t a0, uint32_t a1,
                                         uint32_t a2, uint32_t a3,
                                         uint32_t b0, uint32_t b1) {
    asm volatile(
        "mma.sync.aligned.m16n8k8.row.col.f32.tf32.tf32.f32 "
        "{%0,%1,%2,%3},{%4,%5,%6,%7},{%8,%9},{%0,%1,%2,%3};"
        : "+f"(c[0]), "+f"(c[1]), "+f"(c[2]), "+f"(c[3])
        : "r"(a0), "r"(a1), "r"(a2), "r"(a3), "r"(b0), "r"(b1));
}

__device__ __forceinline__ void split2(float v, float& h, float& l) {
    h = __uint_as_float(__float_as_uint(v) & 0xFFFFE000u);
    l = v - h;
}

__device__ __forceinline__ float tf32_rna(float f) {
    uint32_t r;
    asm("cvt.rna.tf32.f32 %0, %1;" : "=r"(r) : "f"(f));
    return __uint_as_float(r);
}

__device__ __forceinline__ uint32_t fb(float f) { return __float_as_uint(f); }

// ============================================================================
// Kernel 1: ext @ [W_off|W_attn]  (M=128/block, N=192, K=128)
// tf32 3-pass split (AhBh + AlBh + AhBl) ~ fp32 accuracy — precision-critical.
// ============================================================================
__global__ __launch_bounds__(256) void k1_offattn(
    const float* __restrict__ ext, const float* __restrict__ flow,
    const float* __restrict__ W_off, const float* __restrict__ b_off,
    const float* __restrict__ W_attn, const float* __restrict__ b_attn)
{
    extern __shared__ float sm[];
    float* AH = sm;                    // 32*132
    float* AL = AH + 32*LDA;
    float* BH = AL + 32*LDA;           // 32*196
    float* BL = BH + 32*LDB192;

    const int tid  = threadIdx.x;
    const int lane = tid & 31;
    const int warp = tid >> 5;
    const int mw   = warp & 3;
    const int nw   = warp >> 2;
    const int g    = lane >> 2;
    const int tq   = lane & 3;
    const int row0 = blockIdx.x * 128;
    const int b    = row0 / HWQ;
    const int q0   = row0 % HWQ;

    float acc[2][12][4];
#pragma unroll
    for (int t = 0; t < 2; ++t)
#pragma unroll
        for (int j = 0; j < 12; ++j)
#pragma unroll
            for (int v = 0; v < 4; ++v) acc[t][j][v] = 0.f;

    for (int kc = 0; kc < 4; ++kc) {
        {
            const int m4 = (tid & 31) * 4;
            const int kb = tid >> 5;
            const float* src = ext + ((size_t)b*CH + kc*32)*HWQ + q0;
#pragma unroll
            for (int it = 0; it < 4; ++it) {
                int k = kb + it*8;
                float4 v = __ldg((const float4*)(src + (size_t)k*HWQ + m4));
                float4 h, l;
                split2(v.x, h.x, l.x); split2(v.y, h.y, l.y);
                split2(v.z, h.z, l.z); split2(v.w, h.w, l.w);
                *(float4*)(AH + k*LDA + m4) = h;
                *(float4*)(AL + k*LDA + m4) = l;
            }
        }
#pragma unroll
        for (int it = 0; it < 6; ++it) {
            int idx = tid + it*256;            // < 1536
            int k = idx / 48, f4 = idx % 48;
            const float* srcp = (f4 < 32)
                ? W_off  + (size_t)(kc*32 + k)*NOFF + f4*4
                : W_attn + (size_t)(kc*32 + k)*NATT + (f4-32)*4;
            float4 v = __ldg((const float4*)srcp);
            float4 h, l;
            split2(v.x, h.x, l.x); split2(v.y, h.y, l.y);
            split2(v.z, h.z, l.z); split2(v.w, h.w, l.w);
            *(float4*)(BH + k*LDB192 + f4*4) = h;
            *(float4*)(BL + k*LDB192 + f4*4) = l;
        }
        __syncthreads();

#pragma unroll
        for (int k8 = 0; k8 < 4; ++k8) {
            const int kr = k8*8 + tq;
            uint32_t ah[2][4], al[2][4];
#pragma unroll
            for (int t = 0; t < 2; ++t) {
                int m = mw*32 + t*16 + g;
                ah[t][0] = fb(AH[kr*LDA + m]);     ah[t][1] = fb(AH[kr*LDA + m + 8]);
                ah[t][2] = fb(AH[(kr+4)*LDA + m]); ah[t][3] = fb(AH[(kr+4)*LDA + m + 8]);
                al[t][0] = fb(AL[kr*LDA + m]);     al[t][1] = fb(AL[kr*LDA + m + 8]);
                al[t][2] = fb(AL[(kr+4)*LDA + m]); al[t][3] = fb(AL[(kr+4)*LDA + m + 8]);
            }
            uint32_t bh[12][2], bl[12][2];
#pragma unroll
            for (int j = 0; j < 12; ++j) {
                int n = nw*96 + j*8 + g;
                bh[j][0] = fb(BH[kr*LDB192 + n]); bh[j][1] = fb(BH[(kr+4)*LDB192 + n]);
                bl[j][0] = fb(BL[kr*LDB192 + n]); bl[j][1] = fb(BL[(kr+4)*LDB192 + n]);
            }
#pragma unroll
            for (int t = 0; t < 2; ++t)
#pragma unroll
                for (int j = 0; j < 12; ++j) {
                    mma_tf32(acc[t][j], ah[t][0],ah[t][1],ah[t][2],ah[t][3], bh[j][0],bh[j][1]);
                    mma_tf32(acc[t][j], al[t][0],al[t][1],al[t][2],al[t][3], bh[j][0],bh[j][1]);
                    mma_tf32(acc[t][j], ah[t][0],ah[t][1],ah[t][2],ah[t][3], bl[j][0],bl[j][1]);
                }
        }
        __syncthreads();
    }

    int   qrow[4]; float fxv[4], fyv[4]; float wiv[4], hiv[4];
#pragma unroll
    for (int t = 0; t < 2; ++t)
#pragma unroll
        for (int rr = 0; rr < 2; ++rr) {
            int r  = mw*32 + t*16 + g + rr*8;
            int qq = q0 + r;
            int ri = t*2 + rr;
            qrow[ri] = qq;
            fxv[ri] = __ldg(&flow[(size_t)b*2*HWQ + qq]);
            fyv[ri] = __ldg(&flow[(size_t)b*2*HWQ + HWQ + qq]);
            wiv[ri] = (float)(qq & (WW-1));
            hiv[ri] = (float)((qq >> 7) & (HH-1));
        }

#pragma unroll
    for (int j = 0; j < 12; ++j) {
        int c = nw*96 + j*8 + 2*tq;
        if (c < NOFF) {
            int n = c >> 1;
            float b0v = __ldg(&b_off[c]), b1v = __ldg(&b_off[c+1]);
#pragma unroll
            for (int t = 0; t < 2; ++t)
#pragma unroll
                for (int rr = 0; rr < 2; ++rr) {
                    int ri = t*2 + rr;
                    float ox = MAXRES * tanhf(acc[t][j][rr*2]   + b0v);
                    float oy = MAXRES * tanhf(acc[t][j][rr*2+1] + b1v);
                    float lx = (wiv[ri] + 0.5f + fxv[ri] + ox) * (1.f/WW);
                    float ly = (hiv[ri] + 0.5f + fyv[ri] + oy) * (1.f/HH);
                    d_loc[((size_t)b*HWQ + qrow[ri])*NATT + n] = make_float2(lx, ly);
                }
        } else {
            int ca = c - NOFF;
            float ba0 = __ldg(&b_attn[ca]), ba1 = __ldg(&b_attn[ca+1]);
#pragma unroll
            for (int t = 0; t < 2; ++t)
#pragma unroll
                for (int rr = 0; rr < 2; ++rr) {
                    float v0 = acc[t][j][rr*2]   + ba0;
                    float v1 = acc[t][j][rr*2+1] + ba1;
                    float mx = fmaxf(v0, v1);
                    mx = fmaxf(mx, __shfl_xor_sync(0xffffffffu, mx, 1));
                    mx = fmaxf(mx, __shfl_xor_sync(0xffffffffu, mx, 2));
                    float e0 = __expf(v0 - mx), e1 = __expf(v1 - mx);
                    float s = e0 + e1;
                    s += __shfl_xor_sync(0xffffffffu, s, 1);
                    s += __shfl_xor_sync(0xffffffffu, s, 2);
                    float inv = 1.f / s;
                    *(float2*)&d_attn[((size_t)b*HWQ + qrow[t*2+rr])*NATT + ca] =
                        make_float2(e0*inv, e1*inv);
                }
        }
    }
}

// ============================================================================
// Kernel 2: val = nbr @ W_val + b_val  (N=128), tf32 2-pass; fp16 output
// ============================================================================
__global__ __launch_bounds__(256) void k_val(
    const float* __restrict__ nbr,
    const float* __restrict__ W_val, const float* __restrict__ b_val)
{
    extern __shared__ float sm[];
    float* AH = sm;
    float* AL = AH + 32*LDA;
    float* BS = AL + 32*LDA;

    const int tid  = threadIdx.x;
    const int lane = tid & 31;
    const int warp = tid >> 5;
    const int mw   = warp & 3;
    const int nw   = warp >> 2;
    const int g    = lane >> 2;
    const int tq   = lane & 3;
    const int row0 = blockIdx.x * 128;
    const int b    = row0 / HWQ;
    const int q0   = row0 % HWQ;

    float acc[2][8][4];
#pragma unroll
    for (int t = 0; t < 2; ++t)
#pragma unroll
        for (int j = 0; j < 8; ++j)
#pragma unroll
            for (int v = 0; v < 4; ++v) acc[t][j][v] = 0.f;

    for (int kc = 0; kc < 4; ++kc) {
        {
            const int m4 = (tid & 31) * 4;
            const int kb = tid >> 5;
            const float* src = nbr + ((size_t)b*CH + kc*32)*HWQ + q0;
#pragma unroll
            for (int it = 0; it < 4; ++it) {
                int k = kb + it*8;
                float4 v = __ldg((const float4*)(src + (size_t)k*HWQ + m4));
                float4 h, l;
                split2(v.x, h.x, l.x); split2(v.y, h.y, l.y);
                split2(v.z, h.z, l.z); split2(v.w, h.w, l.w);
                *(float4*)(AH + k*LDA + m4) = h;
                *(float4*)(AL + k*LDA + m4) = l;
            }
        }
#pragma unroll
        for (int it = 0; it < 4; ++it) {
            int idx = tid + it*256;
            int k = idx >> 5, f4 = idx & 31;
            float4 v = __ldg((const float4*)(W_val + (size_t)(kc*32 + k)*CH + f4*4));
            v.x = tf32_rna(v.x); v.y = tf32_rna(v.y);
            v.z = tf32_rna(v.z); v.w = tf32_rna(v.w);
            *(float4*)(BS + k*LDB128 + f4*4) = v;
        }
        __syncthreads();

#pragma unroll
        for (int k8 = 0; k8 < 4; ++k8) {
            const int kr = k8*8 + tq;
            uint32_t ah[2][4], al[2][4];
#pragma unroll
            for (int t = 0; t < 2; ++t) {
                int m = mw*32 + t*16 + g;
                ah[t][0] = fb(AH[kr*LDA + m]);     ah[t][1] = fb(AH[kr*LDA + m + 8]);
                ah[t][2] = fb(AH[(kr+4)*LDA + m]); ah[t][3] = fb(AH[(kr+4)*LDA + m + 8]);
                al[t][0] = fb(AL[kr*LDA + m]);     al[t][1] = fb(AL[kr*LDA + m + 8]);
                al[t][2] = fb(AL[(kr+4)*LDA + m]); al[t][3] = fb(AL[(kr+4)*LDA + m + 8]);
            }
            uint32_t bs[8][2];
#pragma unroll
            for (int j = 0; j < 8; ++j) {
                int n = nw*64 + j*8 + g;
                bs[j][0] = fb(BS[kr*LDB128 + n]); bs[j][1] = fb(BS[(kr+4)*LDB128 + n]);
            }
#pragma unroll
            for (int t = 0; t < 2; ++t)
#pragma unroll
                for (int j = 0; j < 8; ++j) {
                    mma_tf32(acc[t][j], ah[t][0],ah[t][1],ah[t][2],ah[t][3], bs[j][0],bs[j][1]);
                    mma_tf32(acc[t][j], al[t][0],al[t][1],al[t][2],al[t][3], bs[j][0],bs[j][1]);
                }
        }
        __syncthreads();
    }

#pragma unroll
    for (int j = 0; j < 8; ++j) {
        int c = nw*64 + j*8 + 2*tq;
        float b0v = __ldg(&b_val[c]), b1v = __ldg(&b_val[c+1]);
#pragma unroll
        for (int t = 0; t < 2; ++t)
#pragma unroll
            for (int rr = 0; rr < 2; ++rr) {
                int r = row0 + mw*32 + t*16 + g + rr*8;
                __half2 hv = __floats2half2_rn(acc[t][j][rr*2] + b0v,
                                               acc[t][j][rr*2+1] + b1v);
                *(__half2*)&d_val_h[(size_t)r*CH + c] = hv;
            }
    }
}

// ============================================================================
// Kernel 3: bilinear gather (fp16 values) + attention aggregation.
// 256 threads = 16 q x 16 channel-groups (8 ch each). Flat 1D q mapping.
// ============================================================================
__device__ __forceinline__ void gacc(float w, const __half* p, float* acc) {
    uint4 gg = __ldg((const uint4*)p);
    float2 f;
    f = __half22float2(*(__half2*)&gg.x); acc[0]=fmaf(w,f.x,acc[0]); acc[1]=fmaf(w,f.y,acc[1]);
    f = __half22float2(*(((__half2*)&gg.x)+1)); acc[2]=fmaf(w,f.x,acc[2]); acc[3]=fmaf(w,f.y,acc[3]);
    f = __half22float2(*(__half2*)&gg.z); acc[4]=fmaf(w,f.x,acc[4]); acc[5]=fmaf(w,f.y,acc[5]);
    f = __half22float2(*(((__half2*)&gg.z)+1)); acc[6]=fmaf(w,f.x,acc[6]); acc[7]=fmaf(w,f.y,acc[7]);
}

__global__ __launch_bounds__(256) void k_gather()
{
    __shared__ float2 loc_s[16][NATT];
    __shared__ float  attn_s[16][NATT];
    const int tx = threadIdx.x;
    const size_t base = (size_t)blockIdx.x * 16;   // global (b*Q+q) base

    for (int i = tx; i < 1024; i += 256) {
        int tq = i >> 6, n = i & 63;
        loc_s[tq][n]  = d_loc [(base + tq)*NATT + n];
        attn_s[tq][n] = d_attn[(base + tq)*NATT + n];
    }
    __syncthreads();

    const int tq = tx >> 4;                 // 0..15
    const int c2 = tx & 15;                 // 8-channel group
    const int h  = c2 >> 1;
    const size_t row = base + tq;
    const int b  = (int)(row >> 14);
    const __half* vb = d_val_h + (size_t)b * HWQ * CH + c2*8;

    float acc[8];
#pragma unroll
    for (int i = 0; i < 8; ++i) acc[i] = 0.f;

#pragma unroll
    for (int p = 0; p < NPNT; ++p) {
        int n = h*NPNT + p;
        float2 l = loc_s[tq][n];
        float  a = attn_s[tq][n];
        float x = l.x * (float)WW - 0.5f;
        float y = l.y * (float)HH - 0.5f;
        float x0f = floorf(x), y0f = floorf(y);
        float wx = x - x0f,    wy = y - y0f;
        int x0 = (int)x0f, y0 = (int)y0f;
        int x1 = x0 + 1,   y1 = y0 + 1;
        bool xv0 = (x0 >= 0) & (x0 < WW);
        bool xv1 = (x1 >= 0) & (x1 < WW);
        bool yv0 = (y0 >= 0) & (y0 < HH);
        bool yv1 = (y1 >= 0) & (y1 < HH);
        float w00 = (1.f-wx)*(1.f-wy) * a;
        float w10 = wx*(1.f-wy) * a;
        float w01 = (1.f-wx)*wy * a;
        float w11 = wx*wy * a;
        if (xv0 & yv0) gacc(w00, vb + (size_t)(y0*WW + x0)*CH, acc);
        if (xv1 & yv0) gacc(w10, vb + (size_t)(y0*WW + x1)*CH, acc);
        if (xv0 & yv1) gacc(w01, vb + (size_t)(y1*WW + x0)*CH, acc);
        if (xv1 & yv1) gacc(w11, vb + (size_t)(y1*WW + x1)*CH, acc);
    }
    float* dst = d_agg + row*CH + c2*8;
    *(float4*)dst     = make_float4(acc[0], acc[1], acc[2], acc[3]);
    *(float4*)(dst+4) = make_float4(acc[4], acc[5], acc[6], acc[7]);
}

// ============================================================================
// Kernel 4: out = agg @ W_out + b_out, transposed store (N=128)
// ============================================================================
__global__ __launch_bounds__(256) void k_out(
    const float* __restrict__ W_out, const float* __restrict__ b_out,
    float* __restrict__ out)
{
    extern __shared__ float sm[];
    float* AH = sm;
    float* AL = AH + 32*LDA;
    float* BS = AL + 32*LDA;

    const int tid  = threadIdx.x;
    const int lane = tid & 31;
    const int warp = tid >> 5;
    const int mw   = warp & 3;
    const int nw   = warp >> 2;
    const int g    = lane >> 2;
    const int tq   = lane & 3;
    const int row0 = blockIdx.x * 128;
    const int b    = row0 / HWQ;
    const int q0   = row0 % HWQ;

    float acc[2][8][4];
#pragma unroll
    for (int t = 0; t < 2; ++t)
#pragma unroll
        for (int j = 0; j < 8; ++j)
#pragma unroll
            for (int v = 0; v < 4; ++v) acc[t][j][v] = 0.f;

    for (int kc = 0; kc < 4; ++kc) {
        {
            const int m  = tid & 127;
            const int g0 = tid >> 7;
            const float* src = d_agg + (size_t)(row0 + m)*CH + kc*32;
#pragma unroll
            for (int it = 0; it < 4; ++it) {
                int gg = g0 + it*2;
                float4 v = *(const float4*)(src + gg*4);
                float h, l;
                split2(v.x, h, l); AH[(gg*4+0)*LDA + m] = h; AL[(gg*4+0)*LDA + m] = l;
                split2(v.y, h, l); AH[(gg*4+1)*LDA + m] = h; AL[(gg*4+1)*LDA + m] = l;
                split2(v.z, h, l); AH[(gg*4+2)*LDA + m] = h; AL[(gg*4+2)*LDA + m] = l;
                split2(v.w, h, l); AH[(gg*4+3)*LDA + m] = h; AL[(gg*4+3)*LDA + m] = l;
            }
        }
#pragma unroll
        for (int it = 0; it < 4; ++it) {
            int idx = tid + it*256;
            int k = idx >> 5, f4 = idx & 31;
            float4 v = __ldg((const float4*)(W_out + (size_t)(kc*32 + k)*CH + f4*4));
            v.x = tf32_rna(v.x); v.y = tf32_rna(v.y);
            v.z = tf32_rna(v.z); v.w = tf32_rna(v.w);
            *(float4*)(BS + k*LDB128 + f4*4) = v;
        }
        __syncthreads();

#pragma unroll
        for (int k8 = 0; k8 < 4; ++k8) {
            const int kr = k8*8 + tq;
            uint32_t ah[2][4], al[2][4];
#pragma unroll
            for (int t = 0; t < 2; ++t) {
                int m = mw*32 + t*16 + g;
                ah[t][0] = fb(AH[kr*LDA + m]);     ah[t][1] = fb(AH[kr*LDA + m + 8]);
                ah[t][2] = fb(AH[(kr+4)*LDA + m]); ah[t][3] = fb(AH[(kr+4)*LDA + m + 8]);
                al[t][0] = fb(AL[kr*LDA + m]);     al[t][1] = fb(AL[kr*LDA + m + 8]);
                al[t][2] = fb(AL[(kr+4)*LDA + m]); al[t][3] = fb(AL[(kr+4)*LDA + m + 8]);
            }
            uint32_t bs[8][2];
#pragma unroll
            for (int j = 0; j < 8; ++j) {
                int n = nw*64 + j*8 + g;
                bs[j][0] = fb(BS[kr*LDB128 + n]); bs[j][1] = fb(BS[(kr+4)*LDB128 + n]);
            }
#pragma unroll
            for (int t = 0; t < 2; ++t)
#pragma unroll
                for (int j = 0; j < 8; ++j) {
                    mma_tf32(acc[t][j], ah[t][0],ah[t][1],ah[t][2],ah[t][3], bs[j][0],bs[j][1]);
                    mma_tf32(acc[t][j], al[t][0],al[t][1],al[t][2],al[t][3], bs[j][0],bs[j][1]);
                }
        }
        __syncthreads();
    }

    float* buf = sm;                       // reuse; 128*129 floats
#pragma unroll
    for (int j = 0; j < 8; ++j) {
        int c = nw*64 + j*8 + 2*tq;
        float b0v = __ldg(&b_out[c]), b1v = __ldg(&b_out[c+1]);
#pragma unroll
        for (int t = 0; t < 2; ++t)
#pragma unroll
            for (int rr = 0; rr < 2; ++rr) {
                int m = mw*32 + t*16 + g + rr*8;
                buf[m*129 + c]     = acc[t][j][rr*2]   + b0v;
                buf[m*129 + c + 1] = acc[t][j][rr*2+1] + b1v;
            }
    }
    __syncthreads();
    for (int idx = tid; idx < 128*128; idx += 256) {
        int m = idx & 127, n = idx >> 7;
        out[(size_t)b*CH*HWQ + (size_t)n*HWQ + q0 + m] = buf[m*129 + n];
    }
}

// ============================================================================
extern "C" void kernel_launch(void* const* d_in, const int* in_sizes, int n_in,
                              void* d_out, int out_size)
{
    const float* nbr    = (const float*)d_in[0];
    const float* ext    = (const float*)d_in[1];
    const float* flow   = (const float*)d_in[2];
    const float* W_off  = (const float*)d_in[3];
    const float* b_off  = (const float*)d_in[4];
    const float* W_attn = (const float*)d_in[5];
    const float* b_attn = (const float*)d_in[6];
    const float* W_val  = (const float*)d_in[7];
    const float* b_val  = (const float*)d_in[8];
    const float* W_out  = (const float*)d_in[9];
    const float* b_out  = (const float*)d_in[10];
    float* out = (float*)d_out;

    const int SM_K1 = (2*32*LDA + 2*32*LDB192) * 4;              // 83968
    const int SM_KV = (2*32*LDA + 32*LDB128) * 4;                // 50688
    const int SM_KO_MMA = (2*32*LDA + 32*LDB128) * 4;
    const int SM_KO_BUF = 128*129*4;                              // 66048
    const int SM_KO = SM_KO_BUF > SM_KO_MMA ? SM_KO_BUF : SM_KO_MMA;

    cudaFuncSetAttribute(k1_offattn, cudaFuncAttributeMaxDynamicSharedMemorySize, SM_K1);
    cudaFuncSetAttribute(k_val,      cudaFuncAttributeMaxDynamicSharedMemorySize, SM_KV);
    cudaFuncSetAttribute(k_out,      cudaFuncAttributeMaxDynamicSharedMemorySize, SM_KO);

    const int nblk = BATCH * HWQ / 128;   // 512

    k1_offattn<<<nblk, 256, SM_K1>>>(ext, flow, W_off, b_off, W_attn, b_attn);
    k_val     <<<nblk, 256, SM_KV>>>(nbr, W_val, b_val);
    k_gather  <<<BATCH * HWQ / 16, 256>>>();
    k_out     <<<nblk, 256, SM_KO>>>(W_out, b_out, out);
}

// round 10
// speedup vs baseline: 1.1788x; 1.1549x over previous
#include <cuda_runtime.h>
#include <cuda_fp16.h>
#include <math.h>
#include <stdint.h>

#define BATCH 4
#define CH    128
#define HH    128
#define WW    128
#define HWQ   16384
#define NHEAD 8
#define NPNT  8
#define NOFF  128
#define NATT  64
#define MAXRES 10.0f

// conflict-free k-major strides (floats): stride%32 == 8 -> fragment reads
// hit banks tq*8+g (all distinct). 4-byte*stride %16==0 keeps cp16 dst aligned.
#define LDA136 136
#define LDB200 200
#define LDB136 136
#define LDA133 133   // k_out A (4B cp.async transpose stage: k*5+m distinct banks)

// ---- scratch ----
__device__ __half d_val_h[(size_t)BATCH * HWQ * CH];
__device__ float  d_agg [(size_t)BATCH * HWQ * CH];
__device__ float2 d_loc [(size_t)BATCH * HWQ * NATT];
__device__ float  d_attn[(size_t)BATCH * HWQ * NATT];

// ============================================================================
// helpers
// ============================================================================
__device__ __forceinline__ void mma_tf32(float* c, uint32_t a0, uint32_t a1,
                                         uint32_t a2, uint32_t a3,
                                         uint32_t b0, uint32_t b1) {
    asm volatile(
        "mma.sync.aligned.m16n8k8.row.col.f32.tf32.tf32.f32 "
        "{%0,%1,%2,%3},{%4,%5,%6,%7},{%8,%9},{%0,%1,%2,%3};"
        : "+f"(c[0]), "+f"(c[1]), "+f"(c[2]), "+f"(c[3])
        : "r"(a0), "r"(a1), "r"(a2), "r"(a3), "r"(b0), "r"(b1));
}

__device__ __forceinline__ void split2(float v, float& h, float& l) {
    h = __uint_as_float(__float_as_uint(v) & 0xFFFFE000u);
    l = v - h;
}
__device__ __forceinline__ float tf32_rna(float f) {
    uint32_t r;
    asm("cvt.rna.tf32.f32 %0, %1;" : "=r"(r) : "f"(f));
    return __uint_as_float(r);
}
__device__ __forceinline__ uint32_t fb(float f) { return __float_as_uint(f); }

__device__ __forceinline__ void cp16(uint32_t dst, const void* src) {
    asm volatile("cp.async.ca.shared.global [%0], [%1], 16;" :: "r"(dst), "l"(src));
}
__device__ __forceinline__ void cp4(uint32_t dst, const void* src) {
    asm volatile("cp.async.ca.shared.global [%0], [%1], 4;" :: "r"(dst), "l"(src));
}
#define CP_COMMIT() asm volatile("cp.async.commit_group;" ::: "memory")
#define CP_WAIT1()  asm volatile("cp.async.wait_group 1;" ::: "memory")
#define CP_WAIT0()  asm volatile("cp.async.wait_group 0;" ::: "memory")

// ============================================================================
// Kernel 1: ext @ [W_off|W_attn]  (M=128/block, N=192, K=128)
// tf32 3-pass (AhBh + AlBh + AhBl), splits done IN REGISTERS from raw smem.
// cp.async double-buffered staging.
// ============================================================================
#define K1_ABUF (32*LDA136)              // 4352 floats
#define K1_BBUF (32*LDB200)              // 6400 floats
#define K1_STG  (K1_ABUF + K1_BBUF)      // 10752 floats per buffer

__global__ __launch_bounds__(256) void k1_offattn(
    const float* __restrict__ ext, const float* __restrict__ flow,
    const float* __restrict__ W_off, const float* __restrict__ b_off,
    const float* __restrict__ W_attn, const float* __restrict__ b_attn)
{
    extern __shared__ float sm[];
    const int tid  = threadIdx.x;
    const int lane = tid & 31;
    const int warp = tid >> 5;
    const int mw   = warp & 3;
    const int nw   = warp >> 2;
    const int g    = lane >> 2;
    const int tq   = lane & 3;
    const int row0 = blockIdx.x * 128;
    const int b    = row0 / HWQ;
    const int q0   = row0 % HWQ;
    const uint32_t smb = (uint32_t)__cvta_generic_to_shared(sm);

    float acc[2][12][4];
#pragma unroll
    for (int t = 0; t < 2; ++t)
#pragma unroll
        for (int j = 0; j < 12; ++j)
#pragma unroll
            for (int v = 0; v < 4; ++v) acc[t][j][v] = 0.f;

    // ---- staging lambda-ish macros ----
    auto stage = [&](int kc, int buf) {
        uint32_t ab = smb + (uint32_t)(buf*K1_STG)*4u;
        const float* srcA = ext + ((size_t)b*CH + kc*32)*HWQ + q0;
#pragma unroll
        for (int it = 0; it < 4; ++it) {
            int e = tid + it*256;              // < 1024 chunks of 16B
            int k = e >> 5, c4 = e & 31;
            cp16(ab + (uint32_t)(k*LDA136 + c4*4)*4u, srcA + (size_t)k*HWQ + c4*4);
        }
        uint32_t bb = smb + (uint32_t)(buf*K1_STG + K1_ABUF)*4u;
#pragma unroll
        for (int it = 0; it < 6; ++it) {
            int e = tid + it*256;              // < 1536
            int k = e / 48, f4 = e % 48;
            const float* srcp = (f4 < 32)
                ? W_off  + (size_t)(kc*32 + k)*NOFF + f4*4
                : W_attn + (size_t)(kc*32 + k)*NATT + (f4-32)*4;
            cp16(bb + (uint32_t)(k*LDB200 + f4*4)*4u, srcp);
        }
    };

    stage(0, 0); CP_COMMIT();
    for (int kc = 0; kc < 4; ++kc) {
        if (kc < 3) { stage(kc+1, (kc+1)&1); CP_COMMIT(); CP_WAIT1(); }
        else CP_WAIT0();
        __syncthreads();
        const float* As = sm + (kc&1)*K1_STG;
        const float* Bs = As + K1_ABUF;

#pragma unroll
        for (int k8 = 0; k8 < 4; ++k8) {
            const int kr = k8*8 + tq;
            uint32_t ah[2][4], al[2][4];
#pragma unroll
            for (int t = 0; t < 2; ++t) {
                int m = mw*32 + t*16 + g;
                float h, l;
                split2(As[kr*LDA136 + m], h, l);         ah[t][0]=fb(h); al[t][0]=fb(l);
                split2(As[kr*LDA136 + m + 8], h, l);     ah[t][1]=fb(h); al[t][1]=fb(l);
                split2(As[(kr+4)*LDA136 + m], h, l);     ah[t][2]=fb(h); al[t][2]=fb(l);
                split2(As[(kr+4)*LDA136 + m + 8], h, l); ah[t][3]=fb(h); al[t][3]=fb(l);
            }
            uint32_t bh[12][2], bl[12][2];
#pragma unroll
            for (int j = 0; j < 12; ++j) {
                int n = nw*96 + j*8 + g;
                float h, l;
                split2(Bs[kr*LDB200 + n], h, l);     bh[j][0]=fb(h); bl[j][0]=fb(l);
                split2(Bs[(kr+4)*LDB200 + n], h, l); bh[j][1]=fb(h); bl[j][1]=fb(l);
            }
#pragma unroll
            for (int t = 0; t < 2; ++t)
#pragma unroll
                for (int j = 0; j < 12; ++j) {
                    mma_tf32(acc[t][j], ah[t][0],ah[t][1],ah[t][2],ah[t][3], bh[j][0],bh[j][1]);
                    mma_tf32(acc[t][j], al[t][0],al[t][1],al[t][2],al[t][3], bh[j][0],bh[j][1]);
                    mma_tf32(acc[t][j], ah[t][0],ah[t][1],ah[t][2],ah[t][3], bl[j][0],bl[j][1]);
                }
        }
        if (kc < 3) __syncthreads();
    }

    // ---- epilogue ----
    int   qrow[4]; float fxv[4], fyv[4]; float wiv[4], hiv[4];
#pragma unroll
    for (int t = 0; t < 2; ++t)
#pragma unroll
        for (int rr = 0; rr < 2; ++rr) {
            int r  = mw*32 + t*16 + g + rr*8;
            int qq = q0 + r;
            int ri = t*2 + rr;
            qrow[ri] = qq;
            fxv[ri] = __ldg(&flow[(size_t)b*2*HWQ + qq]);
            fyv[ri] = __ldg(&flow[(size_t)b*2*HWQ + HWQ + qq]);
            wiv[ri] = (float)(qq & (WW-1));
            hiv[ri] = (float)((qq >> 7) & (HH-1));
        }

#pragma unroll
    for (int j = 0; j < 12; ++j) {
        int c = nw*96 + j*8 + 2*tq;
        if (c < NOFF) {
            int n = c >> 1;
            float b0v = __ldg(&b_off[c]), b1v = __ldg(&b_off[c+1]);
#pragma unroll
            for (int t = 0; t < 2; ++t)
#pragma unroll
                for (int rr = 0; rr < 2; ++rr) {
                    int ri = t*2 + rr;
                    float ox = MAXRES * tanhf(acc[t][j][rr*2]   + b0v);
                    float oy = MAXRES * tanhf(acc[t][j][rr*2+1] + b1v);
                    float lx = (wiv[ri] + 0.5f + fxv[ri] + ox) * (1.f/WW);
                    float ly = (hiv[ri] + 0.5f + fyv[ri] + oy) * (1.f/HH);
                    d_loc[((size_t)b*HWQ + qrow[ri])*NATT + n] = make_float2(lx, ly);
                }
        } else {
            int ca = c - NOFF;
            float ba0 = __ldg(&b_attn[ca]), ba1 = __ldg(&b_attn[ca+1]);
#pragma unroll
            for (int t = 0; t < 2; ++t)
#pragma unroll
                for (int rr = 0; rr < 2; ++rr) {
                    float v0 = acc[t][j][rr*2]   + ba0;
                    float v1 = acc[t][j][rr*2+1] + ba1;
                    float mx = fmaxf(v0, v1);
                    mx = fmaxf(mx, __shfl_xor_sync(0xffffffffu, mx, 1));
                    mx = fmaxf(mx, __shfl_xor_sync(0xffffffffu, mx, 2));
                    float e0 = __expf(v0 - mx), e1 = __expf(v1 - mx);
                    float s = e0 + e1;
                    s += __shfl_xor_sync(0xffffffffu, s, 1);
                    s += __shfl_xor_sync(0xffffffffu, s, 2);
                    float inv = 1.f / s;
                    *(float2*)&d_attn[((size_t)b*HWQ + qrow[t*2+rr])*NATT + ca] =
                        make_float2(e0*inv, e1*inv);
                }
        }
    }
}

// ============================================================================
// Kernel 2: val = nbr @ W_val + b_val  (N=128), tf32 2-pass, fp16 output.
// cp.async double-buffered; A split + B rna in registers.
// ============================================================================
#define KV_ABUF (32*LDA136)
#define KV_BBUF (32*LDB136)
#define KV_STG  (KV_ABUF + KV_BBUF)      // 8704 floats

__global__ __launch_bounds__(256) void k_val(
    const float* __restrict__ nbr,
    const float* __restrict__ W_val, const float* __restrict__ b_val)
{
    extern __shared__ float sm[];
    const int tid  = threadIdx.x;
    const int lane = tid & 31;
    const int warp = tid >> 5;
    const int mw   = warp & 3;
    const int nw   = warp >> 2;
    const int g    = lane >> 2;
    const int tq   = lane & 3;
    const int row0 = blockIdx.x * 128;
    const int b    = row0 / HWQ;
    const int q0   = row0 % HWQ;
    const uint32_t smb = (uint32_t)__cvta_generic_to_shared(sm);

    float acc[2][8][4];
#pragma unroll
    for (int t = 0; t < 2; ++t)
#pragma unroll
        for (int j = 0; j < 8; ++j)
#pragma unroll
            for (int v = 0; v < 4; ++v) acc[t][j][v] = 0.f;

    auto stage = [&](int kc, int buf) {
        uint32_t ab = smb + (uint32_t)(buf*KV_STG)*4u;
        const float* srcA = nbr + ((size_t)b*CH + kc*32)*HWQ + q0;
#pragma unroll
        for (int it = 0; it < 4; ++it) {
            int e = tid + it*256;
            int k = e >> 5, c4 = e & 31;
            cp16(ab + (uint32_t)(k*LDA136 + c4*4)*4u, srcA + (size_t)k*HWQ + c4*4);
        }
        uint32_t bb = smb + (uint32_t)(buf*KV_STG + KV_ABUF)*4u;
#pragma unroll
        for (int it = 0; it < 4; ++it) {
            int e = tid + it*256;
            int k = e >> 5, c4 = e & 31;
            cp16(bb + (uint32_t)(k*LDB136 + c4*4)*4u,
                 W_val + (size_t)(kc*32 + k)*CH + c4*4);
        }
    };

    stage(0, 0); CP_COMMIT();
    for (int kc = 0; kc < 4; ++kc) {
        if (kc < 3) { stage(kc+1, (kc+1)&1); CP_COMMIT(); CP_WAIT1(); }
        else CP_WAIT0();
        __syncthreads();
        const float* As = sm + (kc&1)*KV_STG;
        const float* Bs = As + KV_ABUF;

#pragma unroll
        for (int k8 = 0; k8 < 4; ++k8) {
            const int kr = k8*8 + tq;
            uint32_t ah[2][4], al[2][4];
#pragma unroll
            for (int t = 0; t < 2; ++t) {
                int m = mw*32 + t*16 + g;
                float h, l;
                split2(As[kr*LDA136 + m], h, l);         ah[t][0]=fb(h); al[t][0]=fb(l);
                split2(As[kr*LDA136 + m + 8], h, l);     ah[t][1]=fb(h); al[t][1]=fb(l);
                split2(As[(kr+4)*LDA136 + m], h, l);     ah[t][2]=fb(h); al[t][2]=fb(l);
                split2(As[(kr+4)*LDA136 + m + 8], h, l); ah[t][3]=fb(h); al[t][3]=fb(l);
            }
            uint32_t bs[8][2];
#pragma unroll
            for (int j = 0; j < 8; ++j) {
                int n = nw*64 + j*8 + g;
                bs[j][0] = fb(tf32_rna(Bs[kr*LDB136 + n]));
                bs[j][1] = fb(tf32_rna(Bs[(kr+4)*LDB136 + n]));
            }
#pragma unroll
            for (int t = 0; t < 2; ++t)
#pragma unroll
                for (int j = 0; j < 8; ++j) {
                    mma_tf32(acc[t][j], ah[t][0],ah[t][1],ah[t][2],ah[t][3], bs[j][0],bs[j][1]);
                    mma_tf32(acc[t][j], al[t][0],al[t][1],al[t][2],al[t][3], bs[j][0],bs[j][1]);
                }
        }
        if (kc < 3) __syncthreads();
    }

#pragma unroll
    for (int j = 0; j < 8; ++j) {
        int c = nw*64 + j*8 + 2*tq;
        float b0v = __ldg(&b_val[c]), b1v = __ldg(&b_val[c+1]);
#pragma unroll
        for (int t = 0; t < 2; ++t)
#pragma unroll
            for (int rr = 0; rr < 2; ++rr) {
                int r = row0 + mw*32 + t*16 + g + rr*8;
                __half2 hv = __floats2half2_rn(acc[t][j][rr*2] + b0v,
                                               acc[t][j][rr*2+1] + b1v);
                *(__half2*)&d_val_h[(size_t)r*CH + c] = hv;
            }
    }
}

// ============================================================================
// Kernel 3: bilinear gather (fp16 values) + attention aggregation (R8 version)
// ============================================================================
__device__ __forceinline__ void gacc(float w, const __half* p, float* acc) {
    uint4 gg = __ldg((const uint4*)p);
    float2 f;
    f = __half22float2(*(__half2*)&gg.x); acc[0]=fmaf(w,f.x,acc[0]); acc[1]=fmaf(w,f.y,acc[1]);
    f = __half22float2(*(((__half2*)&gg.x)+1)); acc[2]=fmaf(w,f.x,acc[2]); acc[3]=fmaf(w,f.y,acc[3]);
    f = __half22float2(*(__half2*)&gg.z); acc[4]=fmaf(w,f.x,acc[4]); acc[5]=fmaf(w,f.y,acc[5]);
    f = __half22float2(*(((__half2*)&gg.z)+1)); acc[6]=fmaf(w,f.x,acc[6]); acc[7]=fmaf(w,f.y,acc[7]);
}

__global__ __launch_bounds__(256) void k_gather()
{
    __shared__ float2 loc_s[16][NATT];
    __shared__ float  attn_s[16][NATT];
    const int tx = threadIdx.x;
    const size_t base = (size_t)blockIdx.x * 16;

    for (int i = tx; i < 1024; i += 256) {
        int tq = i >> 6, n = i & 63;
        loc_s[tq][n]  = d_loc [(base + tq)*NATT + n];
        attn_s[tq][n] = d_attn[(base + tq)*NATT + n];
    }
    __syncthreads();

    const int tq = tx >> 4;
    const int c2 = tx & 15;
    const int h  = c2 >> 1;
    const size_t row = base + tq;
    const int b  = (int)(row >> 14);
    const __half* vb = d_val_h + (size_t)b * HWQ * CH + c2*8;

    float acc[8];
#pragma unroll
    for (int i = 0; i < 8; ++i) acc[i] = 0.f;

#pragma unroll
    for (int p = 0; p < NPNT; ++p) {
        int n = h*NPNT + p;
        float2 l = loc_s[tq][n];
        float  a = attn_s[tq][n];
        float x = l.x * (float)WW - 0.5f;
        float y = l.y * (float)HH - 0.5f;
        float x0f = floorf(x), y0f = floorf(y);
        float wx = x - x0f,    wy = y - y0f;
        int x0 = (int)x0f, y0 = (int)y0f;
        int x1 = x0 + 1,   y1 = y0 + 1;
        bool xv0 = (x0 >= 0) & (x0 < WW);
        bool xv1 = (x1 >= 0) & (x1 < WW);
        bool yv0 = (y0 >= 0) & (y0 < HH);
        bool yv1 = (y1 >= 0) & (y1 < HH);
        float w00 = (1.f-wx)*(1.f-wy) * a;
        float w10 = wx*(1.f-wy) * a;
        float w01 = (1.f-wx)*wy * a;
        float w11 = wx*wy * a;
        if (xv0 & yv0) gacc(w00, vb + (size_t)(y0*WW + x0)*CH, acc);
        if (xv1 & yv0) gacc(w10, vb + (size_t)(y0*WW + x1)*CH, acc);
        if (xv0 & yv1) gacc(w01, vb + (size_t)(y1*WW + x0)*CH, acc);
        if (xv1 & yv1) gacc(w11, vb + (size_t)(y1*WW + x1)*CH, acc);
    }
    float* dst = d_agg + row*CH + c2*8;
    *(float4*)dst     = make_float4(acc[0], acc[1], acc[2], acc[3]);
    *(float4*)(dst+4) = make_float4(acc[4], acc[5], acc[6], acc[7]);
}

// ============================================================================
// Kernel 4: out = agg @ W_out + b_out (N=128), transposed store.
// cp.async double-buffered; A transpose-staged with 4B cp.async (stride 133).
// ============================================================================
#define KO_ABUF (32*LDA133)              // 4256 floats
#define KO_BBUF (32*LDB136)              // 4352 floats
#define KO_STG  (KO_ABUF + KO_BBUF)      // 8608 floats

__global__ __launch_bounds__(256) void k_out(
    const float* __restrict__ W_out, const float* __restrict__ b_out,
    float* __restrict__ out)
{
    extern __shared__ float sm[];
    const int tid  = threadIdx.x;
    const int lane = tid & 31;
    const int warp = tid >> 5;
    const int mw   = warp & 3;
    const int nw   = warp >> 2;
    const int g    = lane >> 2;
    const int tq   = lane & 3;
    const int row0 = blockIdx.x * 128;
    const int b    = row0 / HWQ;
    const int q0   = row0 % HWQ;
    const uint32_t smb = (uint32_t)__cvta_generic_to_shared(sm);

    float acc[2][8][4];
#pragma unroll
    for (int t = 0; t < 2; ++t)
#pragma unroll
        for (int j = 0; j < 8; ++j)
#pragma unroll
            for (int v = 0; v < 4; ++v) acc[t][j][v] = 0.f;

    auto stage = [&](int kc, int buf) {
        uint32_t ab = smb + (uint32_t)(buf*KO_STG)*4u;
        const float* srcA = d_agg + (size_t)row0*CH + kc*32;
#pragma unroll
        for (int it = 0; it < 16; ++it) {
            int e = tid + it*256;              // 4096 elements
            int m = e >> 5, k = e & 31;        // consecutive tid -> consecutive k (coalesced)
            cp4(ab + (uint32_t)(k*LDA133 + m)*4u, srcA + (size_t)m*CH + k);
        }
        uint32_t bb = smb + (uint32_t)(buf*KO_STG + KO_ABUF)*4u;
#pragma unroll
        for (int it = 0; it < 4; ++it) {
            int e = tid + it*256;
            int k = e >> 5, c4 = e & 31;
            cp16(bb + (uint32_t)(k*LDB136 + c4*4)*4u,
                 W_out + (size_t)(kc*32 + k)*CH + c4*4);
        }
    };

    stage(0, 0); CP_COMMIT();
    for (int kc = 0; kc < 4; ++kc) {
        if (kc < 3) { stage(kc+1, (kc+1)&1); CP_COMMIT(); CP_WAIT1(); }
        else CP_WAIT0();
        __syncthreads();
        const float* As = sm + (kc&1)*KO_STG;
        const float* Bs = As + KO_ABUF;

#pragma unroll
        for (int k8 = 0; k8 < 4; ++k8) {
            const int kr = k8*8 + tq;
            uint32_t ah[2][4], al[2][4];
#pragma unroll
            for (int t = 0; t < 2; ++t) {
                int m = mw*32 + t*16 + g;
                float h, l;
                split2(As[kr*LDA133 + m], h, l);         ah[t][0]=fb(h); al[t][0]=fb(l);
                split2(As[kr*LDA133 + m + 8], h, l);     ah[t][1]=fb(h); al[t][1]=fb(l);
                split2(As[(kr+4)*LDA133 + m], h, l);     ah[t][2]=fb(h); al[t][2]=fb(l);
                split2(As[(kr+4)*LDA133 + m + 8], h, l); ah[t][3]=fb(h); al[t][3]=fb(l);
            }
            uint32_t bs[8][2];
#pragma unroll
            for (int j = 0; j < 8; ++j) {
                int n = nw*64 + j*8 + g;
                bs[j][0] = fb(tf32_rna(Bs[kr*LDB136 + n]));
                bs[j][1] = fb(tf32_rna(Bs[(kr+4)*LDB136 + n]));
            }
#pragma unroll
            for (int t = 0; t < 2; ++t)
#pragma unroll
                for (int j = 0; j < 8; ++j) {
                    mma_tf32(acc[t][j], ah[t][0],ah[t][1],ah[t][2],ah[t][3], bs[j][0],bs[j][1]);
                    mma_tf32(acc[t][j], al[t][0],al[t][1],al[t][2],al[t][3], bs[j][0],bs[j][1]);
                }
        }
        __syncthreads();
    }

    // stage (acc + bias) into buf[m][129], then coalesced transposed store
    float* buf = sm;                       // reuse; 128*129 = 16512 floats <= KO smem
#pragma unroll
    for (int j = 0; j < 8; ++j) {
        int c = nw*64 + j*8 + 2*tq;
        float b0v = __ldg(&b_out[c]), b1v = __ldg(&b_out[c+1]);
#pragma unroll
        for (int t = 0; t < 2; ++t)
#pragma unroll
            for (int rr = 0; rr < 2; ++rr) {
                int m = mw*32 + t*16 + g + rr*8;
                buf[m*129 + c]     = acc[t][j][rr*2]   + b0v;
                buf[m*129 + c + 1] = acc[t][j][rr*2+1] + b1v;
            }
    }
    __syncthreads();
    for (int idx = tid; idx < 128*128; idx += 256) {
        int m = idx & 127, n = idx >> 7;
        out[(size_t)b*CH*HWQ + (size_t)n*HWQ + q0 + m] = buf[m*129 + n];
    }
}

// ============================================================================
extern "C" void kernel_launch(void* const* d_in, const int* in_sizes, int n_in,
                              void* d_out, int out_size)
{
    const float* nbr    = (const float*)d_in[0];
    const float* ext    = (const float*)d_in[1];
    const float* flow   = (const float*)d_in[2];
    const float* W_off  = (const float*)d_in[3];
    const float* b_off  = (const float*)d_in[4];
    const float* W_attn = (const float*)d_in[5];
    const float* b_attn = (const float*)d_in[6];
    const float* W_val  = (const float*)d_in[7];
    const float* b_val  = (const float*)d_in[8];
    const float* W_out  = (const float*)d_in[9];
    const float* b_out  = (const float*)d_in[10];
    float* out = (float*)d_out;

    const int SM_K1 = 2*K1_STG*4;        // 86016 B
    const int SM_KV = 2*KV_STG*4;        // 69632 B
    const int SM_KO = 2*KO_STG*4;        // 68864 B (>= 66048 epilogue buf)

    cudaFuncSetAttribute(k1_offattn, cudaFuncAttributeMaxDynamicSharedMemorySize, SM_K1);
    cudaFuncSetAttribute(k_val,      cudaFuncAttributeMaxDynamicSharedMemorySize, SM_KV);
    cudaFuncSetAttribute(k_out,      cudaFuncAttributeMaxDynamicSharedMemorySize, SM_KO);

    const int nblk = BATCH * HWQ / 128;   // 512

    k1_offattn<<<nblk, 256, SM_K1>>>(ext, flow, W_off, b_off, W_attn, b_attn);
    k_val     <<<nblk, 256, SM_KV>>>(nbr, W_val, b_val);
    k_gather  <<<BATCH * HWQ / 16, 256>>>();
    k_out     <<<nblk, 256, SM_KO>>>(W_out, b_out, out);
}

// round 11
// speedup vs baseline: 1.2324x; 1.0454x over previous
#include <cuda_runtime.h>
#include <cuda_fp16.h>
#include <math.h>
#include <stdint.h>

#define BATCH 4
#define CH    128
#define HH    128
#define WW    128
#define HWQ   16384
#define NHEAD 8
#define NPNT  8
#define NOFF  128
#define NATT  64
#define MAXRES 10.0f

// conflict-free k-major strides (floats): stride%32 == 8 -> fragment reads
// hit banks tq*8+g (all distinct). 4-byte*stride %16==0 keeps cp16 dst aligned.
#define LDA136 136
#define LDB200 200
#define LDB136 136
#define LDA133 133   // k_out A (4B cp.async transpose stage: k*5+m distinct banks)

// ---- scratch ----
__device__ __half d_val_h[(size_t)BATCH * HWQ * CH];
__device__ float  d_agg [(size_t)BATCH * HWQ * CH];
__device__ float2 d_loc [(size_t)BATCH * HWQ * NATT];
__device__ float  d_attn[(size_t)BATCH * HWQ * NATT];

// ============================================================================
// helpers
// ============================================================================
__device__ __forceinline__ void mma_tf32(float* c, uint32_t a0, uint32_t a1,
                                         uint32_t a2, uint32_t a3,
                                         uint32_t b0, uint32_t b1) {
    asm volatile(
        "mma.sync.aligned.m16n8k8.row.col.f32.tf32.tf32.f32 "
        "{%0,%1,%2,%3},{%4,%5,%6,%7},{%8,%9},{%0,%1,%2,%3};"
        : "+f"(c[0]), "+f"(c[1]), "+f"(c[2]), "+f"(c[3])
        : "r"(a0), "r"(a1), "r"(a2), "r"(a3), "r"(b0), "r"(b1));
}

__device__ __forceinline__ void split2(float v, float& h, float& l) {
    h = __uint_as_float(__float_as_uint(v) & 0xFFFFE000u);
    l = v - h;
}
__device__ __forceinline__ float tf32_rna(float f) {
    uint32_t r;
    asm("cvt.rna.tf32.f32 %0, %1;" : "=r"(r) : "f"(f));
    return __uint_as_float(r);
}
__device__ __forceinline__ uint32_t fb(float f) { return __float_as_uint(f); }

__device__ __forceinline__ void cp16(uint32_t dst, const void* src) {
    asm volatile("cp.async.ca.shared.global [%0], [%1], 16;" :: "r"(dst), "l"(src));
}
__device__ __forceinline__ void cp4(uint32_t dst, const void* src) {
    asm volatile("cp.async.ca.shared.global [%0], [%1], 4;" :: "r"(dst), "l"(src));
}
#define CP_COMMIT() asm volatile("cp.async.commit_group;" ::: "memory")
#define CP_WAIT1()  asm volatile("cp.async.wait_group 1;" ::: "memory")
#define CP_WAIT0()  asm volatile("cp.async.wait_group 0;" ::: "memory")

// ============================================================================
// Kernel 1: ext @ [W_off|W_attn]  (M=128/block, N=192, K=128)
// tf32 3-pass (AhBh + AlBh + AhBl), splits in registers; cp.async dbl-buffer.
// __launch_bounds__(256,2): cap regs at 128 -> 2 CTAs/SM.
// ============================================================================
#define K1_ABUF (32*LDA136)              // 4352 floats
#define K1_BBUF (32*LDB200)              // 6400 floats
#define K1_STG  (K1_ABUF + K1_BBUF)      // 10752 floats per buffer

__global__ __launch_bounds__(256, 2) void k1_offattn(
    const float* __restrict__ ext, const float* __restrict__ flow,
    const float* __restrict__ W_off, const float* __restrict__ b_off,
    const float* __restrict__ W_attn, const float* __restrict__ b_attn)
{
    extern __shared__ float sm[];
    const int tid  = threadIdx.x;
    const int lane = tid & 31;
    const int warp = tid >> 5;
    const int mw   = warp & 3;
    const int nw   = warp >> 2;
    const int g    = lane >> 2;
    const int tq   = lane & 3;
    const int row0 = blockIdx.x * 128;
    const int b    = row0 / HWQ;
    const int q0   = row0 % HWQ;
    const uint32_t smb = (uint32_t)__cvta_generic_to_shared(sm);

    float acc[2][12][4];
#pragma unroll
    for (int t = 0; t < 2; ++t)
#pragma unroll
        for (int j = 0; j < 12; ++j)
#pragma unroll
            for (int v = 0; v < 4; ++v) acc[t][j][v] = 0.f;

    auto stage = [&](int kc, int buf) {
        uint32_t ab = smb + (uint32_t)(buf*K1_STG)*4u;
        const float* srcA = ext + ((size_t)b*CH + kc*32)*HWQ + q0;
#pragma unroll
        for (int it = 0; it < 4; ++it) {
            int e = tid + it*256;              // < 1024 chunks of 16B
            int k = e >> 5, c4 = e & 31;
            cp16(ab + (uint32_t)(k*LDA136 + c4*4)*4u, srcA + (size_t)k*HWQ + c4*4);
        }
        uint32_t bb = smb + (uint32_t)(buf*K1_STG + K1_ABUF)*4u;
#pragma unroll
        for (int it = 0; it < 6; ++it) {
            int e = tid + it*256;              // < 1536
            int k = e / 48, f4 = e % 48;
            const float* srcp = (f4 < 32)
                ? W_off  + (size_t)(kc*32 + k)*NOFF + f4*4
                : W_attn + (size_t)(kc*32 + k)*NATT + (f4-32)*4;
            cp16(bb + (uint32_t)(k*LDB200 + f4*4)*4u, srcp);
        }
    };

    stage(0, 0); CP_COMMIT();
    for (int kc = 0; kc < 4; ++kc) {
        if (kc < 3) { stage(kc+1, (kc+1)&1); CP_COMMIT(); CP_WAIT1(); }
        else CP_WAIT0();
        __syncthreads();
        const float* As = sm + (kc&1)*K1_STG;
        const float* Bs = As + K1_ABUF;

#pragma unroll
        for (int k8 = 0; k8 < 4; ++k8) {
            const int kr = k8*8 + tq;
            uint32_t ah[2][4], al[2][4];
#pragma unroll
            for (int t = 0; t < 2; ++t) {
                int m = mw*32 + t*16 + g;
                float h, l;
                split2(As[kr*LDA136 + m], h, l);         ah[t][0]=fb(h); al[t][0]=fb(l);
                split2(As[kr*LDA136 + m + 8], h, l);     ah[t][1]=fb(h); al[t][1]=fb(l);
                split2(As[(kr+4)*LDA136 + m], h, l);     ah[t][2]=fb(h); al[t][2]=fb(l);
                split2(As[(kr+4)*LDA136 + m + 8], h, l); ah[t][3]=fb(h); al[t][3]=fb(l);
            }
#pragma unroll
            for (int j = 0; j < 12; ++j) {
                int n = nw*96 + j*8 + g;
                float bh0, bl0, bh1, bl1;
                split2(Bs[kr*LDB200 + n], bh0, bl0);
                split2(Bs[(kr+4)*LDB200 + n], bh1, bl1);
#pragma unroll
                for (int t = 0; t < 2; ++t) {
                    mma_tf32(acc[t][j], ah[t][0],ah[t][1],ah[t][2],ah[t][3], fb(bh0),fb(bh1));
                    mma_tf32(acc[t][j], al[t][0],al[t][1],al[t][2],al[t][3], fb(bh0),fb(bh1));
                    mma_tf32(acc[t][j], ah[t][0],ah[t][1],ah[t][2],ah[t][3], fb(bl0),fb(bl1));
                }
            }
        }
        if (kc < 3) __syncthreads();
    }

    // ---- epilogue ----
    int   qrow[4]; float fxv[4], fyv[4]; float wiv[4], hiv[4];
#pragma unroll
    for (int t = 0; t < 2; ++t)
#pragma unroll
        for (int rr = 0; rr < 2; ++rr) {
            int r  = mw*32 + t*16 + g + rr*8;
            int qq = q0 + r;
            int ri = t*2 + rr;
            qrow[ri] = qq;
            fxv[ri] = __ldg(&flow[(size_t)b*2*HWQ + qq]);
            fyv[ri] = __ldg(&flow[(size_t)b*2*HWQ + HWQ + qq]);
            wiv[ri] = (float)(qq & (WW-1));
            hiv[ri] = (float)((qq >> 7) & (HH-1));
        }

#pragma unroll
    for (int j = 0; j < 12; ++j) {
        int c = nw*96 + j*8 + 2*tq;
        if (c < NOFF) {
            int n = c >> 1;
            float b0v = __ldg(&b_off[c]), b1v = __ldg(&b_off[c+1]);
#pragma unroll
            for (int t = 0; t < 2; ++t)
#pragma unroll
                for (int rr = 0; rr < 2; ++rr) {
                    int ri = t*2 + rr;
                    float ox = MAXRES * tanhf(acc[t][j][rr*2]   + b0v);
                    float oy = MAXRES * tanhf(acc[t][j][rr*2+1] + b1v);
                    float lx = (wiv[ri] + 0.5f + fxv[ri] + ox) * (1.f/WW);
                    float ly = (hiv[ri] + 0.5f + fyv[ri] + oy) * (1.f/HH);
                    d_loc[((size_t)b*HWQ + qrow[ri])*NATT + n] = make_float2(lx, ly);
                }
        } else {
            int ca = c - NOFF;
            float ba0 = __ldg(&b_attn[ca]), ba1 = __ldg(&b_attn[ca+1]);
#pragma unroll
            for (int t = 0; t < 2; ++t)
#pragma unroll
                for (int rr = 0; rr < 2; ++rr) {
                    float v0 = acc[t][j][rr*2]   + ba0;
                    float v1 = acc[t][j][rr*2+1] + ba1;
                    float mx = fmaxf(v0, v1);
                    mx = fmaxf(mx, __shfl_xor_sync(0xffffffffu, mx, 1));
                    mx = fmaxf(mx, __shfl_xor_sync(0xffffffffu, mx, 2));
                    float e0 = __expf(v0 - mx), e1 = __expf(v1 - mx);
                    float s = e0 + e1;
                    s += __shfl_xor_sync(0xffffffffu, s, 1);
                    s += __shfl_xor_sync(0xffffffffu, s, 2);
                    float inv = 1.f / s;
                    *(float2*)&d_attn[((size_t)b*HWQ + qrow[t*2+rr])*NATT + ca] =
                        make_float2(e0*inv, e1*inv);
                }
        }
    }
}

// ============================================================================
// Kernel 2: val = nbr @ W_val + b_val  (N=128), tf32 2-pass, fp16 output.
// ============================================================================
#define KV_ABUF (32*LDA136)
#define KV_BBUF (32*LDB136)
#define KV_STG  (KV_ABUF + KV_BBUF)      // 8704 floats

__global__ __launch_bounds__(256, 2) void k_val(
    const float* __restrict__ nbr,
    const float* __restrict__ W_val, const float* __restrict__ b_val)
{
    extern __shared__ float sm[];
    const int tid  = threadIdx.x;
    const int lane = tid & 31;
    const int warp = tid >> 5;
    const int mw   = warp & 3;
    const int nw   = warp >> 2;
    const int g    = lane >> 2;
    const int tq   = lane & 3;
    const int row0 = blockIdx.x * 128;
    const int b    = row0 / HWQ;
    const int q0   = row0 % HWQ;
    const uint32_t smb = (uint32_t)__cvta_generic_to_shared(sm);

    float acc[2][8][4];
#pragma unroll
    for (int t = 0; t < 2; ++t)
#pragma unroll
        for (int j = 0; j < 8; ++j)
#pragma unroll
            for (int v = 0; v < 4; ++v) acc[t][j][v] = 0.f;

    auto stage = [&](int kc, int buf) {
        uint32_t ab = smb + (uint32_t)(buf*KV_STG)*4u;
        const float* srcA = nbr + ((size_t)b*CH + kc*32)*HWQ + q0;
#pragma unroll
        for (int it = 0; it < 4; ++it) {
            int e = tid + it*256;
            int k = e >> 5, c4 = e & 31;
            cp16(ab + (uint32_t)(k*LDA136 + c4*4)*4u, srcA + (size_t)k*HWQ + c4*4);
        }
        uint32_t bb = smb + (uint32_t)(buf*KV_STG + KV_ABUF)*4u;
#pragma unroll
        for (int it = 0; it < 4; ++it) {
            int e = tid + it*256;
            int k = e >> 5, c4 = e & 31;
            cp16(bb + (uint32_t)(k*LDB136 + c4*4)*4u,
                 W_val + (size_t)(kc*32 + k)*CH + c4*4);
        }
    };

    stage(0, 0); CP_COMMIT();
    for (int kc = 0; kc < 4; ++kc) {
        if (kc < 3) { stage(kc+1, (kc+1)&1); CP_COMMIT(); CP_WAIT1(); }
        else CP_WAIT0();
        __syncthreads();
        const float* As = sm + (kc&1)*KV_STG;
        const float* Bs = As + KV_ABUF;

#pragma unroll
        for (int k8 = 0; k8 < 4; ++k8) {
            const int kr = k8*8 + tq;
            uint32_t ah[2][4], al[2][4];
#pragma unroll
            for (int t = 0; t < 2; ++t) {
                int m = mw*32 + t*16 + g;
                float h, l;
                split2(As[kr*LDA136 + m], h, l);         ah[t][0]=fb(h); al[t][0]=fb(l);
                split2(As[kr*LDA136 + m + 8], h, l);     ah[t][1]=fb(h); al[t][1]=fb(l);
                split2(As[(kr+4)*LDA136 + m], h, l);     ah[t][2]=fb(h); al[t][2]=fb(l);
                split2(As[(kr+4)*LDA136 + m + 8], h, l); ah[t][3]=fb(h); al[t][3]=fb(l);
            }
#pragma unroll
            for (int j = 0; j < 8; ++j) {
                int n = nw*64 + j*8 + g;
                uint32_t b0 = fb(tf32_rna(Bs[kr*LDB136 + n]));
                uint32_t b1 = fb(tf32_rna(Bs[(kr+4)*LDB136 + n]));
#pragma unroll
                for (int t = 0; t < 2; ++t) {
                    mma_tf32(acc[t][j], ah[t][0],ah[t][1],ah[t][2],ah[t][3], b0,b1);
                    mma_tf32(acc[t][j], al[t][0],al[t][1],al[t][2],al[t][3], b0,b1);
                }
            }
        }
        if (kc < 3) __syncthreads();
    }

#pragma unroll
    for (int j = 0; j < 8; ++j) {
        int c = nw*64 + j*8 + 2*tq;
        float b0v = __ldg(&b_val[c]), b1v = __ldg(&b_val[c+1]);
#pragma unroll
        for (int t = 0; t < 2; ++t)
#pragma unroll
            for (int rr = 0; rr < 2; ++rr) {
                int r = row0 + mw*32 + t*16 + g + rr*8;
                __half2 hv = __floats2half2_rn(acc[t][j][rr*2] + b0v,
                                               acc[t][j][rr*2+1] + b1v);
                *(__half2*)&d_val_h[(size_t)r*CH + c] = hv;
            }
    }
}

// ============================================================================
// Kernel 3: bilinear gather (fp16 values) + attention aggregation
// ============================================================================
__device__ __forceinline__ void gacc(float w, const __half* p, float* acc) {
    uint4 gg = __ldg((const uint4*)p);
    float2 f;
    f = __half22float2(*(__half2*)&gg.x); acc[0]=fmaf(w,f.x,acc[0]); acc[1]=fmaf(w,f.y,acc[1]);
    f = __half22float2(*(((__half2*)&gg.x)+1)); acc[2]=fmaf(w,f.x,acc[2]); acc[3]=fmaf(w,f.y,acc[3]);
    f = __half22float2(*(__half2*)&gg.z); acc[4]=fmaf(w,f.x,acc[4]); acc[5]=fmaf(w,f.y,acc[5]);
    f = __half22float2(*(((__half2*)&gg.z)+1)); acc[6]=fmaf(w,f.x,acc[6]); acc[7]=fmaf(w,f.y,acc[7]);
}

__global__ __launch_bounds__(256) void k_gather()
{
    __shared__ float2 loc_s[16][NATT];
    __shared__ float  attn_s[16][NATT];
    const int tx = threadIdx.x;
    const size_t base = (size_t)blockIdx.x * 16;

    for (int i = tx; i < 1024; i += 256) {
        int tq = i >> 6, n = i & 63;
        loc_s[tq][n]  = d_loc [(base + tq)*NATT + n];
        attn_s[tq][n] = d_attn[(base + tq)*NATT + n];
    }
    __syncthreads();

    const int tq = tx >> 4;
    const int c2 = tx & 15;
    const int h  = c2 >> 1;
    const size_t row = base + tq;
    const int b  = (int)(row >> 14);
    const __half* vb = d_val_h + (size_t)b * HWQ * CH + c2*8;

    float acc[8];
#pragma unroll
    for (int i = 0; i < 8; ++i) acc[i] = 0.f;

#pragma unroll
    for (int p = 0; p < NPNT; ++p) {
        int n = h*NPNT + p;
        float2 l = loc_s[tq][n];
        float  a = attn_s[tq][n];
        float x = l.x * (float)WW - 0.5f;
        float y = l.y * (float)HH - 0.5f;
        float x0f = floorf(x), y0f = floorf(y);
        float wx = x - x0f,    wy = y - y0f;
        int x0 = (int)x0f, y0 = (int)y0f;
        int x1 = x0 + 1,   y1 = y0 + 1;
        bool xv0 = (x0 >= 0) & (x0 < WW);
        bool xv1 = (x1 >= 0) & (x1 < WW);
        bool yv0 = (y0 >= 0) & (y0 < HH);
        bool yv1 = (y1 >= 0) & (y1 < HH);
        float w00 = (1.f-wx)*(1.f-wy) * a;
        float w10 = wx*(1.f-wy) * a;
        float w01 = (1.f-wx)*wy * a;
        float w11 = wx*wy * a;
        if (xv0 & yv0) gacc(w00, vb + (size_t)(y0*WW + x0)*CH, acc);
        if (xv1 & yv0) gacc(w10, vb + (size_t)(y0*WW + x1)*CH, acc);
        if (xv0 & yv1) gacc(w01, vb + (size_t)(y1*WW + x0)*CH, acc);
        if (xv1 & yv1) gacc(w11, vb + (size_t)(y1*WW + x1)*CH, acc);
    }
    float* dst = d_agg + row*CH + c2*8;
    *(float4*)dst     = make_float4(acc[0], acc[1], acc[2], acc[3]);
    *(float4*)(dst+4) = make_float4(acc[4], acc[5], acc[6], acc[7]);
}

// ============================================================================
// Kernel 4: out = agg @ W_out + b_out (N=128), transposed store.
// ============================================================================
#define KO_ABUF (32*LDA133)              // 4256 floats
#define KO_BBUF (32*LDB136)              // 4352 floats
#define KO_STG  (KO_ABUF + KO_BBUF)      // 8608 floats

__global__ __launch_bounds__(256, 2) void k_out(
    const float* __restrict__ W_out, const float* __restrict__ b_out,
    float* __restrict__ out)
{
    extern __shared__ float sm[];
    const int tid  = threadIdx.x;
    const int lane = tid & 31;
    const int warp = tid >> 5;
    const int mw   = warp & 3;
    const int nw   = warp >> 2;
    const int g    = lane >> 2;
    const int tq   = lane & 3;
    const int row0 = blockIdx.x * 128;
    const int b    = row0 / HWQ;
    const int q0   = row0 % HWQ;
    const uint32_t smb = (uint32_t)__cvta_generic_to_shared(sm);

    float acc[2][8][4];
#pragma unroll
    for (int t = 0; t < 2; ++t)
#pragma unroll
        for (int j = 0; j < 8; ++j)
#pragma unroll
            for (int v = 0; v < 4; ++v) acc[t][j][v] = 0.f;

    auto stage = [&](int kc, int buf) {
        uint32_t ab = smb + (uint32_t)(buf*KO_STG)*4u;
        const float* srcA = d_agg + (size_t)row0*CH + kc*32;
#pragma unroll
        for (int it = 0; it < 16; ++it) {
            int e = tid + it*256;              // 4096 elements
            int m = e >> 5, k = e & 31;
            cp4(ab + (uint32_t)(k*LDA133 + m)*4u, srcA + (size_t)m*CH + k);
        }
        uint32_t bb = smb + (uint32_t)(buf*KO_STG + KO_ABUF)*4u;
#pragma unroll
        for (int it = 0; it < 4; ++it) {
            int e = tid + it*256;
            int k = e >> 5, c4 = e & 31;
            cp16(bb + (uint32_t)(k*LDB136 + c4*4)*4u,
                 W_out + (size_t)(kc*32 + k)*CH + c4*4);
        }
    };

    stage(0, 0); CP_COMMIT();
    for (int kc = 0; kc < 4; ++kc) {
        if (kc < 3) { stage(kc+1, (kc+1)&1); CP_COMMIT(); CP_WAIT1(); }
        else CP_WAIT0();
        __syncthreads();
        const float* As = sm + (kc&1)*KO_STG;
        const float* Bs = As + KO_ABUF;

#pragma unroll
        for (int k8 = 0; k8 < 4; ++k8) {
            const int kr = k8*8 + tq;
            uint32_t ah[2][4], al[2][4];
#pragma unroll
            for (int t = 0; t < 2; ++t) {
                int m = mw*32 + t*16 + g;
                float h, l;
                split2(As[kr*LDA133 + m], h, l);         ah[t][0]=fb(h); al[t][0]=fb(l);
                split2(As[kr*LDA133 + m + 8], h, l);     ah[t][1]=fb(h); al[t][1]=fb(l);
                split2(As[(kr+4)*LDA133 + m], h, l);     ah[t][2]=fb(h); al[t][2]=fb(l);
                split2(As[(kr+4)*LDA133 + m + 8], h, l); ah[t][3]=fb(h); al[t][3]=fb(l);
            }
#pragma unroll
            for (int j = 0; j < 8; ++j) {
                int n = nw*64 + j*8 + g;
                uint32_t b0 = fb(tf32_rna(Bs[kr*LDB136 + n]));
                uint32_t b1 = fb(tf32_rna(Bs[(kr+4)*LDB136 + n]));
#pragma unroll
                for (int t = 0; t < 2; ++t) {
                    mma_tf32(acc[t][j], ah[t][0],ah[t][1],ah[t][2],ah[t][3], b0,b1);
                    mma_tf32(acc[t][j], al[t][0],al[t][1],al[t][2],al[t][3], b0,b1);
                }
            }
        }
        __syncthreads();
    }

    // stage (acc + bias) into buf[m][129], then coalesced transposed store
    float* buf = sm;                       // reuse; 128*129 = 16512 floats
#pragma unroll
    for (int j = 0; j < 8; ++j) {
        int c = nw*64 + j*8 + 2*tq;
        float b0v = __ldg(&b_out[c]), b1v = __ldg(&b_out[c+1]);
#pragma unroll
        for (int t = 0; t < 2; ++t)
#pragma unroll
            for (int rr = 0; rr < 2; ++rr) {
                int m = mw*32 + t*16 + g + rr*8;
                buf[m*129 + c]     = acc[t][j][rr*2]   + b0v;
                buf[m*129 + c + 1] = acc[t][j][rr*2+1] + b1v;
            }
    }
    __syncthreads();
    for (int idx = tid; idx < 128*128; idx += 256) {
        int m = idx & 127, n = idx >> 7;
        out[(size_t)b*CH*HWQ + (size_t)n*HWQ + q0 + m] = buf[m*129 + n];
    }
}

// ============================================================================
extern "C" void kernel_launch(void* const* d_in, const int* in_sizes, int n_in,
                              void* d_out, int out_size)
{
    const float* nbr    = (const float*)d_in[0];
    const float* ext    = (const float*)d_in[1];
    const float* flow   = (const float*)d_in[2];
    const float* W_off  = (const float*)d_in[3];
    const float* b_off  = (const float*)d_in[4];
    const float* W_attn = (const float*)d_in[5];
    const float* b_attn = (const float*)d_in[6];
    const float* W_val  = (const float*)d_in[7];
    const float* b_val  = (const float*)d_in[8];
    const float* W_out  = (const float*)d_in[9];
    const float* b_out  = (const float*)d_in[10];
    float* out = (float*)d_out;

    const int SM_K1 = 2*K1_STG*4;        // 86016 B  (x2 CTAs = 172KB < 228KB)
    const int SM_KV = 2*KV_STG*4;        // 69632 B
    const int SM_KO = 2*KO_STG*4;        // 68864 B (>= 66048 epilogue buf)

    cudaFuncSetAttribute(k1_offattn, cudaFuncAttributeMaxDynamicSharedMemorySize, SM_K1);
    cudaFuncSetAttribute(k_val,      cudaFuncAttributeMaxDynamicSharedMemorySize, SM_KV);
    cudaFuncSetAttribute(k_out,      cudaFuncAttributeMaxDynamicSharedMemorySize, SM_KO);

    const int nblk = BATCH * HWQ / 128;   // 512

    k1_offattn<<<nblk, 256, SM_K1>>>(ext, flow, W_off, b_off, W_attn, b_attn);
    k_val     <<<nblk, 256, SM_KV>>>(nbr, W_val, b_val);
    k_gather  <<<BATCH * HWQ / 16, 256>>>();
    k_out     <<<nblk, 256, SM_KO>>>(W_out, b_out, out);
}

// round 12
// speedup vs baseline: 1.3474x; 1.0933x over previous
#include <cuda_runtime.h>
#include <cuda_fp16.h>
#include <math.h>
#include <stdint.h>

#define BATCH 4
#define CH    128
#define HH    128
#define WW    128
#define HWQ   16384
#define NHEAD 8
#define NPNT  8
#define NOFF  128
#define NATT  64
#define MAXRES 10.0f

// conflict-free k-major strides (floats): stride%32 == 8 -> fragment reads
// hit banks tq*8+g (all distinct). 4-byte*stride %16==0 keeps cp16 dst aligned.
#define LDA136 136
#define LDB200 200
#define LDB136 136
#define LDA133 133   // k_out A (4B cp.async transpose stage: k*5+m distinct banks)

// ---- scratch ----
__device__ __half d_val_h[(size_t)BATCH * HWQ * CH];
__device__ float  d_agg [(size_t)BATCH * HWQ * CH];
__device__ float2 d_loc [(size_t)BATCH * HWQ * NATT];
__device__ float  d_attn[(size_t)BATCH * HWQ * NATT];

// ============================================================================
// helpers
// ============================================================================
__device__ __forceinline__ void mma_tf32(float* c, uint32_t a0, uint32_t a1,
                                         uint32_t a2, uint32_t a3,
                                         uint32_t b0, uint32_t b1) {
    asm volatile(
        "mma.sync.aligned.m16n8k8.row.col.f32.tf32.tf32.f32 "
        "{%0,%1,%2,%3},{%4,%5,%6,%7},{%8,%9},{%0,%1,%2,%3};"
        : "+f"(c[0]), "+f"(c[1]), "+f"(c[2]), "+f"(c[3])
        : "r"(a0), "r"(a1), "r"(a2), "r"(a3), "r"(b0), "r"(b1));
}

__device__ __forceinline__ void split2(float v, float& h, float& l) {
    h = __uint_as_float(__float_as_uint(v) & 0xFFFFE000u);
    l = v - h;
}
__device__ __forceinline__ float tf32_rna(float f) {
    uint32_t r;
    asm("cvt.rna.tf32.f32 %0, %1;" : "=r"(r) : "f"(f));
    return __uint_as_float(r);
}
__device__ __forceinline__ uint32_t fbrna(float f) {
    uint32_t r;
    asm("cvt.rna.tf32.f32 %0, %1;" : "=r"(r) : "f"(f));
    return r;
}
__device__ __forceinline__ uint32_t fb(float f) { return __float_as_uint(f); }

__device__ __forceinline__ void cp16(uint32_t dst, const void* src) {
    asm volatile("cp.async.ca.shared.global [%0], [%1], 16;" :: "r"(dst), "l"(src));
}
__device__ __forceinline__ void cp4(uint32_t dst, const void* src) {
    asm volatile("cp.async.ca.shared.global [%0], [%1], 4;" :: "r"(dst), "l"(src));
}
#define CP_COMMIT() asm volatile("cp.async.commit_group;" ::: "memory")
#define CP_WAIT1()  asm volatile("cp.async.wait_group 1;" ::: "memory")
#define CP_WAIT0()  asm volatile("cp.async.wait_group 0;" ::: "memory")

// ============================================================================
// Kernel 1: ext @ [W_off|W_attn]  (M=128/block, N=192, K=128)
// tf32 3-pass (AhBh + AlBh + AhBl) — precision-critical, DO NOT downgrade
// (R6 measured 1.02e-3 with 2-pass here).
// ============================================================================
#define K1_ABUF (32*LDA136)              // 4352 floats
#define K1_BBUF (32*LDB200)              // 6400 floats
#define K1_STG  (K1_ABUF + K1_BBUF)      // 10752 floats per buffer

__global__ __launch_bounds__(256, 2) void k1_offattn(
    const float* __restrict__ ext, const float* __restrict__ flow,
    const float* __restrict__ W_off, const float* __restrict__ b_off,
    const float* __restrict__ W_attn, const float* __restrict__ b_attn)
{
    extern __shared__ float sm[];
    const int tid  = threadIdx.x;
    const int lane = tid & 31;
    const int warp = tid >> 5;
    const int mw   = warp & 3;
    const int nw   = warp >> 2;
    const int g    = lane >> 2;
    const int tq   = lane & 3;
    const int row0 = blockIdx.x * 128;
    const int b    = row0 / HWQ;
    const int q0   = row0 % HWQ;
    const uint32_t smb = (uint32_t)__cvta_generic_to_shared(sm);

    float acc[2][12][4];
#pragma unroll
    for (int t = 0; t < 2; ++t)
#pragma unroll
        for (int j = 0; j < 12; ++j)
#pragma unroll
            for (int v = 0; v < 4; ++v) acc[t][j][v] = 0.f;

    auto stage = [&](int kc, int buf) {
        uint32_t ab = smb + (uint32_t)(buf*K1_STG)*4u;
        const float* srcA = ext + ((size_t)b*CH + kc*32)*HWQ + q0;
#pragma unroll
        for (int it = 0; it < 4; ++it) {
            int e = tid + it*256;              // < 1024 chunks of 16B
            int k = e >> 5, c4 = e & 31;
            cp16(ab + (uint32_t)(k*LDA136 + c4*4)*4u, srcA + (size_t)k*HWQ + c4*4);
        }
        uint32_t bb = smb + (uint32_t)(buf*K1_STG + K1_ABUF)*4u;
#pragma unroll
        for (int it = 0; it < 6; ++it) {
            int e = tid + it*256;              // < 1536
            int k = e / 48, f4 = e % 48;
            const float* srcp = (f4 < 32)
                ? W_off  + (size_t)(kc*32 + k)*NOFF + f4*4
                : W_attn + (size_t)(kc*32 + k)*NATT + (f4-32)*4;
            cp16(bb + (uint32_t)(k*LDB200 + f4*4)*4u, srcp);
        }
    };

    stage(0, 0); CP_COMMIT();
    for (int kc = 0; kc < 4; ++kc) {
        if (kc < 3) { stage(kc+1, (kc+1)&1); CP_COMMIT(); CP_WAIT1(); }
        else CP_WAIT0();
        __syncthreads();
        const float* As = sm + (kc&1)*K1_STG;
        const float* Bs = As + K1_ABUF;

#pragma unroll
        for (int k8 = 0; k8 < 4; ++k8) {
            const int kr = k8*8 + tq;
            uint32_t ah[2][4], al[2][4];
#pragma unroll
            for (int t = 0; t < 2; ++t) {
                int m = mw*32 + t*16 + g;
                float h, l;
                split2(As[kr*LDA136 + m], h, l);         ah[t][0]=fb(h); al[t][0]=fb(l);
                split2(As[kr*LDA136 + m + 8], h, l);     ah[t][1]=fb(h); al[t][1]=fb(l);
                split2(As[(kr+4)*LDA136 + m], h, l);     ah[t][2]=fb(h); al[t][2]=fb(l);
                split2(As[(kr+4)*LDA136 + m + 8], h, l); ah[t][3]=fb(h); al[t][3]=fb(l);
            }
#pragma unroll
            for (int j = 0; j < 12; ++j) {
                int n = nw*96 + j*8 + g;
                float bh0, bl0, bh1, bl1;
                split2(Bs[kr*LDB200 + n], bh0, bl0);
                split2(Bs[(kr+4)*LDB200 + n], bh1, bl1);
#pragma unroll
                for (int t = 0; t < 2; ++t) {
                    mma_tf32(acc[t][j], ah[t][0],ah[t][1],ah[t][2],ah[t][3], fb(bh0),fb(bh1));
                    mma_tf32(acc[t][j], al[t][0],al[t][1],al[t][2],al[t][3], fb(bh0),fb(bh1));
                    mma_tf32(acc[t][j], ah[t][0],ah[t][1],ah[t][2],ah[t][3], fb(bl0),fb(bl1));
                }
            }
        }
        if (kc < 3) __syncthreads();
    }

    // ---- epilogue ----
    int   qrow[4]; float fxv[4], fyv[4]; float wiv[4], hiv[4];
#pragma unroll
    for (int t = 0; t < 2; ++t)
#pragma unroll
        for (int rr = 0; rr < 2; ++rr) {
            int r  = mw*32 + t*16 + g + rr*8;
            int qq = q0 + r;
            int ri = t*2 + rr;
            qrow[ri] = qq;
            fxv[ri] = __ldg(&flow[(size_t)b*2*HWQ + qq]);
            fyv[ri] = __ldg(&flow[(size_t)b*2*HWQ + HWQ + qq]);
            wiv[ri] = (float)(qq & (WW-1));
            hiv[ri] = (float)((qq >> 7) & (HH-1));
        }

#pragma unroll
    for (int j = 0; j < 12; ++j) {
        int c = nw*96 + j*8 + 2*tq;
        if (c < NOFF) {
            int n = c >> 1;
            float b0v = __ldg(&b_off[c]), b1v = __ldg(&b_off[c+1]);
#pragma unroll
            for (int t = 0; t < 2; ++t)
#pragma unroll
                for (int rr = 0; rr < 2; ++rr) {
                    int ri = t*2 + rr;
                    float ox = MAXRES * tanhf(acc[t][j][rr*2]   + b0v);
                    float oy = MAXRES * tanhf(acc[t][j][rr*2+1] + b1v);
                    float lx = (wiv[ri] + 0.5f + fxv[ri] + ox) * (1.f/WW);
                    float ly = (hiv[ri] + 0.5f + fyv[ri] + oy) * (1.f/HH);
                    d_loc[((size_t)b*HWQ + qrow[ri])*NATT + n] = make_float2(lx, ly);
                }
        } else {
            int ca = c - NOFF;
            float ba0 = __ldg(&b_attn[ca]), ba1 = __ldg(&b_attn[ca+1]);
#pragma unroll
            for (int t = 0; t < 2; ++t)
#pragma unroll
                for (int rr = 0; rr < 2; ++rr) {
                    float v0 = acc[t][j][rr*2]   + ba0;
                    float v1 = acc[t][j][rr*2+1] + ba1;
                    float mx = fmaxf(v0, v1);
                    mx = fmaxf(mx, __shfl_xor_sync(0xffffffffu, mx, 1));
                    mx = fmaxf(mx, __shfl_xor_sync(0xffffffffu, mx, 2));
                    float e0 = __expf(v0 - mx), e1 = __expf(v1 - mx);
                    float s = e0 + e1;
                    s += __shfl_xor_sync(0xffffffffu, s, 1);
                    s += __shfl_xor_sync(0xffffffffu, s, 2);
                    float inv = 1.f / s;
                    *(float2*)&d_attn[((size_t)b*HWQ + qrow[t*2+rr])*NATT + ca] =
                        make_float2(e0*inv, e1*inv);
                }
        }
    }
}

// ============================================================================
// Kernel 2: val = nbr @ W_val + b_val  (N=128), SINGLE-pass tf32 (A+B rna).
// Output is fp16-quantized (4.9e-4) -> tf32 A error (~6e-5) is below the
// existing noise floor. fp16 output.
// ============================================================================
#define KV_ABUF (32*LDA136)
#define KV_BBUF (32*LDB136)
#define KV_STG  (KV_ABUF + KV_BBUF)      // 8704 floats

__global__ __launch_bounds__(256, 2) void k_val(
    const float* __restrict__ nbr,
    const float* __restrict__ W_val, const float* __restrict__ b_val)
{
    extern __shared__ float sm[];
    const int tid  = threadIdx.x;
    const int lane = tid & 31;
    const int warp = tid >> 5;
    const int mw   = warp & 3;
    const int nw   = warp >> 2;
    const int g    = lane >> 2;
    const int tq   = lane & 3;
    const int row0 = blockIdx.x * 128;
    const int b    = row0 / HWQ;
    const int q0   = row0 % HWQ;
    const uint32_t smb = (uint32_t)__cvta_generic_to_shared(sm);

    float acc[2][8][4];
#pragma unroll
    for (int t = 0; t < 2; ++t)
#pragma unroll
        for (int j = 0; j < 8; ++j)
#pragma unroll
            for (int v = 0; v < 4; ++v) acc[t][j][v] = 0.f;

    auto stage = [&](int kc, int buf) {
        uint32_t ab = smb + (uint32_t)(buf*KV_STG)*4u;
        const float* srcA = nbr + ((size_t)b*CH + kc*32)*HWQ + q0;
#pragma unroll
        for (int it = 0; it < 4; ++it) {
            int e = tid + it*256;
            int k = e >> 5, c4 = e & 31;
            cp16(ab + (uint32_t)(k*LDA136 + c4*4)*4u, srcA + (size_t)k*HWQ + c4*4);
        }
        uint32_t bb = smb + (uint32_t)(buf*KV_STG + KV_ABUF)*4u;
#pragma unroll
        for (int it = 0; it < 4; ++it) {
            int e = tid + it*256;
            int k = e >> 5, c4 = e & 31;
            cp16(bb + (uint32_t)(k*LDB136 + c4*4)*4u,
                 W_val + (size_t)(kc*32 + k)*CH + c4*4);
        }
    };

    stage(0, 0); CP_COMMIT();
    for (int kc = 0; kc < 4; ++kc) {
        if (kc < 3) { stage(kc+1, (kc+1)&1); CP_COMMIT(); CP_WAIT1(); }
        else CP_WAIT0();
        __syncthreads();
        const float* As = sm + (kc&1)*KV_STG;
        const float* Bs = As + KV_ABUF;

#pragma unroll
        for (int k8 = 0; k8 < 4; ++k8) {
            const int kr = k8*8 + tq;
            uint32_t av[2][4];
#pragma unroll
            for (int t = 0; t < 2; ++t) {
                int m = mw*32 + t*16 + g;
                av[t][0] = fbrna(As[kr*LDA136 + m]);
                av[t][1] = fbrna(As[kr*LDA136 + m + 8]);
                av[t][2] = fbrna(As[(kr+4)*LDA136 + m]);
                av[t][3] = fbrna(As[(kr+4)*LDA136 + m + 8]);
            }
#pragma unroll
            for (int j = 0; j < 8; ++j) {
                int n = nw*64 + j*8 + g;
                uint32_t b0 = fbrna(Bs[kr*LDB136 + n]);
                uint32_t b1 = fbrna(Bs[(kr+4)*LDB136 + n]);
#pragma unroll
                for (int t = 0; t < 2; ++t)
                    mma_tf32(acc[t][j], av[t][0],av[t][1],av[t][2],av[t][3], b0,b1);
            }
        }
        if (kc < 3) __syncthreads();
    }

#pragma unroll
    for (int j = 0; j < 8; ++j) {
        int c = nw*64 + j*8 + 2*tq;
        float b0v = __ldg(&b_val[c]), b1v = __ldg(&b_val[c+1]);
#pragma unroll
        for (int t = 0; t < 2; ++t)
#pragma unroll
            for (int rr = 0; rr < 2; ++rr) {
                int r = row0 + mw*32 + t*16 + g + rr*8;
                __half2 hv = __floats2half2_rn(acc[t][j][rr*2] + b0v,
                                               acc[t][j][rr*2+1] + b1v);
                *(__half2*)&d_val_h[(size_t)r*CH + c] = hv;
            }
    }
}

// ============================================================================
// Kernel 3: bilinear gather (fp16 values) + attention aggregation
// ============================================================================
__device__ __forceinline__ void gacc(float w, const __half* p, float* acc) {
    uint4 gg = __ldg((const uint4*)p);
    float2 f;
    f = __half22float2(*(__half2*)&gg.x); acc[0]=fmaf(w,f.x,acc[0]); acc[1]=fmaf(w,f.y,acc[1]);
    f = __half22float2(*(((__half2*)&gg.x)+1)); acc[2]=fmaf(w,f.x,acc[2]); acc[3]=fmaf(w,f.y,acc[3]);
    f = __half22float2(*(__half2*)&gg.z); acc[4]=fmaf(w,f.x,acc[4]); acc[5]=fmaf(w,f.y,acc[5]);
    f = __half22float2(*(((__half2*)&gg.z)+1)); acc[6]=fmaf(w,f.x,acc[6]); acc[7]=fmaf(w,f.y,acc[7]);
}

__global__ __launch_bounds__(256) void k_gather()
{
    __shared__ float2 loc_s[16][NATT];
    __shared__ float  attn_s[16][NATT];
    const int tx = threadIdx.x;
    const size_t base = (size_t)blockIdx.x * 16;

    for (int i = tx; i < 1024; i += 256) {
        int tq = i >> 6, n = i & 63;
        loc_s[tq][n]  = d_loc [(base + tq)*NATT + n];
        attn_s[tq][n] = d_attn[(base + tq)*NATT + n];
    }
    __syncthreads();

    const int tq = tx >> 4;
    const int c2 = tx & 15;
    const int h  = c2 >> 1;
    const size_t row = base + tq;
    const int b  = (int)(row >> 14);
    const __half* vb = d_val_h + (size_t)b * HWQ * CH + c2*8;

    float acc[8];
#pragma unroll
    for (int i = 0; i < 8; ++i) acc[i] = 0.f;

#pragma unroll
    for (int p = 0; p < NPNT; ++p) {
        int n = h*NPNT + p;
        float2 l = loc_s[tq][n];
        float  a = attn_s[tq][n];
        float x = l.x * (float)WW - 0.5f;
        float y = l.y * (float)HH - 0.5f;
        float x0f = floorf(x), y0f = floorf(y);
        float wx = x - x0f,    wy = y - y0f;
        int x0 = (int)x0f, y0 = (int)y0f;
        int x1 = x0 + 1,   y1 = y0 + 1;
        bool xv0 = (x0 >= 0) & (x0 < WW);
        bool xv1 = (x1 >= 0) & (x1 < WW);
        bool yv0 = (y0 >= 0) & (y0 < HH);
        bool yv1 = (y1 >= 0) & (y1 < HH);
        float w00 = (1.f-wx)*(1.f-wy) * a;
        float w10 = wx*(1.f-wy) * a;
        float w01 = (1.f-wx)*wy * a;
        float w11 = wx*wy * a;
        if (xv0 & yv0) gacc(w00, vb + (size_t)(y0*WW + x0)*CH, acc);
        if (xv1 & yv0) gacc(w10, vb + (size_t)(y0*WW + x1)*CH, acc);
        if (xv0 & yv1) gacc(w01, vb + (size_t)(y1*WW + x0)*CH, acc);
        if (xv1 & yv1) gacc(w11, vb + (size_t)(y1*WW + x1)*CH, acc);
    }
    float* dst = d_agg + row*CH + c2*8;
    *(float4*)dst     = make_float4(acc[0], acc[1], acc[2], acc[3]);
    *(float4*)(dst+4) = make_float4(acc[4], acc[5], acc[6], acc[7]);
}

// ============================================================================
// Kernel 4: out = agg @ W_out + b_out (N=128), SINGLE-pass tf32 (A+B rna).
// d_agg already carries fp16-derived noise (~2e-4) -> tf32 A error negligible.
// ============================================================================
#define KO_ABUF (32*LDA133)              // 4256 floats
#define KO_BBUF (32*LDB136)              // 4352 floats
#define KO_STG  (KO_ABUF + KO_BBUF)      // 8608 floats

__global__ __launch_bounds__(256, 2) void k_out(
    const float* __restrict__ W_out, const float* __restrict__ b_out,
    float* __restrict__ out)
{
    extern __shared__ float sm[];
    const int tid  = threadIdx.x;
    const int lane = tid & 31;
    const int warp = tid >> 5;
    const int mw   = warp & 3;
    const int nw   = warp >> 2;
    const int g    = lane >> 2;
    const int tq   = lane & 3;
    const int row0 = blockIdx.x * 128;
    const int b    = row0 / HWQ;
    const int q0   = row0 % HWQ;
    const uint32_t smb = (uint32_t)__cvta_generic_to_shared(sm);

    float acc[2][8][4];
#pragma unroll
    for (int t = 0; t < 2; ++t)
#pragma unroll
        for (int j = 0; j < 8; ++j)
#pragma unroll
            for (int v = 0; v < 4; ++v) acc[t][j][v] = 0.f;

    auto stage = [&](int kc, int buf) {
        uint32_t ab = smb + (uint32_t)(buf*KO_STG)*4u;
        const float* srcA = d_agg + (size_t)row0*CH + kc*32;
#pragma unroll
        for (int it = 0; it < 16; ++it) {
            int e = tid + it*256;              // 4096 elements
            int m = e >> 5, k = e & 31;
            cp4(ab + (uint32_t)(k*LDA133 + m)*4u, srcA + (size_t)m*CH + k);
        }
        uint32_t bb = smb + (uint32_t)(buf*KO_STG + KO_ABUF)*4u;
#pragma unroll
        for (int it = 0; it < 4; ++it) {
            int e = tid + it*256;
            int k = e >> 5, c4 = e & 31;
            cp16(bb + (uint32_t)(k*LDB136 + c4*4)*4u,
                 W_out + (size_t)(kc*32 + k)*CH + c4*4);
        }
    };

    stage(0, 0); CP_COMMIT();
    for (int kc = 0; kc < 4; ++kc) {
        if (kc < 3) { stage(kc+1, (kc+1)&1); CP_COMMIT(); CP_WAIT1(); }
        else CP_WAIT0();
        __syncthreads();
        const float* As = sm + (kc&1)*KO_STG;
        const float* Bs = As + KO_ABUF;

#pragma unroll
        for (int k8 = 0; k8 < 4; ++k8) {
            const int kr = k8*8 + tq;
            uint32_t av[2][4];
#pragma unroll
            for (int t = 0; t < 2; ++t) {
                int m = mw*32 + t*16 + g;
                av[t][0] = fbrna(As[kr*LDA133 + m]);
                av[t][1] = fbrna(As[kr*LDA133 + m + 8]);
                av[t][2] = fbrna(As[(kr+4)*LDA133 + m]);
                av[t][3] = fbrna(As[(kr+4)*LDA133 + m + 8]);
            }
#pragma unroll
            for (int j = 0; j < 8; ++j) {
                int n = nw*64 + j*8 + g;
                uint32_t b0 = fbrna(Bs[kr*LDB136 + n]);
                uint32_t b1 = fbrna(Bs[(kr+4)*LDB136 + n]);
#pragma unroll
                for (int t = 0; t < 2; ++t)
                    mma_tf32(acc[t][j], av[t][0],av[t][1],av[t][2],av[t][3], b0,b1);
            }
        }
        __syncthreads();
    }

    // stage (acc + bias) into buf[m][129], then coalesced transposed store
    float* buf = sm;                       // reuse; 128*129 = 16512 floats
#pragma unroll
    for (int j = 0; j < 8; ++j) {
        int c = nw*64 + j*8 + 2*tq;
        float b0v = __ldg(&b_out[c]), b1v = __ldg(&b_out[c+1]);
#pragma unroll
        for (int t = 0; t < 2; ++t)
#pragma unroll
            for (int rr = 0; rr < 2; ++rr) {
                int m = mw*32 + t*16 + g + rr*8;
                buf[m*129 + c]     = acc[t][j][rr*2]   + b0v;
                buf[m*129 + c + 1] = acc[t][j][rr*2+1] + b1v;
            }
    }
    __syncthreads();
    for (int idx = tid; idx < 128*128; idx += 256) {
        int m = idx & 127, n = idx >> 7;
        out[(size_t)b*CH*HWQ + (size_t)n*HWQ + q0 + m] = buf[m*129 + n];
    }
}

// ============================================================================
extern "C" void kernel_launch(void* const* d_in, const int* in_sizes, int n_in,
                              void* d_out, int out_size)
{
    const float* nbr    = (const float*)d_in[0];
    const float* ext    = (const float*)d_in[1];
    const float* flow   = (const float*)d_in[2];
    const float* W_off  = (const float*)d_in[3];
    const float* b_off  = (const float*)d_in[4];
    const float* W_attn = (const float*)d_in[5];
    const float* b_attn = (const float*)d_in[6];
    const float* W_val  = (const float*)d_in[7];
    const float* b_val  = (const float*)d_in[8];
    const float* W_out  = (const float*)d_in[9];
    const float* b_out  = (const float*)d_in[10];
    float* out = (float*)d_out;

    const int SM_K1 = 2*K1_STG*4;        // 86016 B  (x2 CTAs = 172KB < 228KB)
    const int SM_KV = 2*KV_STG*4;        // 69632 B
    const int SM_KO = 2*KO_STG*4;        // 68864 B (>= 66048 epilogue buf)

    cudaFuncSetAttribute(k1_offattn, cudaFuncAttributeMaxDynamicSharedMemorySize, SM_K1);
    cudaFuncSetAttribute(k_val,      cudaFuncAttributeMaxDynamicSharedMemorySize, SM_KV);
    cudaFuncSetAttribute(k_out,      cudaFuncAttributeMaxDynamicSharedMemorySize, SM_KO);

    const int nblk = BATCH * HWQ / 128;   // 512

    k1_offattn<<<nblk, 256, SM_K1>>>(ext, flow, W_off, b_off, W_attn, b_attn);
    k_val     <<<nblk, 256, SM_KV>>>(nbr, W_val, b_val);
    k_gather  <<<BATCH * HWQ / 16, 256>>>();
    k_out     <<<nblk, 256, SM_KO>>>(W_out, b_out, out);
}

// round 13
// speedup vs baseline: 1.4237x; 1.0566x over previous
#include <cuda_runtime.h>
#include <cuda_fp16.h>
#include <math.h>
#include <stdint.h>

#define BATCH 4
#define CH    128
#define HH    128
#define WW    128
#define HWQ   16384
#define NHEAD 8
#define NPNT  8
#define NOFF  128
#define NATT  64
#define MAXRES 10.0f

// conflict-free k-major strides (floats): stride%32 == 8 -> fragment reads
// hit banks tq*8+g (all distinct). 4-byte*stride %16==0 keeps cp16 dst aligned.
#define LDA136 136
#define LDB200 200
#define LDB136 136
#define LDA133 133   // k_out A (4B cp.async transpose stage: k*5+m distinct banks)

// ---- scratch ----
__device__ __half d_val_h[(size_t)BATCH * HWQ * CH];
__device__ float  d_agg [(size_t)BATCH * HWQ * CH];
__device__ float2 d_loc [(size_t)BATCH * HWQ * NATT];
__device__ float  d_attn[(size_t)BATCH * HWQ * NATT];

// ============================================================================
// helpers
// ============================================================================
__device__ __forceinline__ void mma_tf32(float* c, uint32_t a0, uint32_t a1,
                                         uint32_t a2, uint32_t a3,
                                         uint32_t b0, uint32_t b1) {
    asm volatile(
        "mma.sync.aligned.m16n8k8.row.col.f32.tf32.tf32.f32 "
        "{%0,%1,%2,%3},{%4,%5,%6,%7},{%8,%9},{%0,%1,%2,%3};"
        : "+f"(c[0]), "+f"(c[1]), "+f"(c[2]), "+f"(c[3])
        : "r"(a0), "r"(a1), "r"(a2), "r"(a3), "r"(b0), "r"(b1));
}

__device__ __forceinline__ void split2(float v, float& h, float& l) {
    h = __uint_as_float(__float_as_uint(v) & 0xFFFFE000u);
    l = v - h;
}
__device__ __forceinline__ uint32_t fbrna(float f) {
    uint32_t r;
    asm("cvt.rna.tf32.f32 %0, %1;" : "=r"(r) : "f"(f));
    return r;
}
__device__ __forceinline__ uint32_t fb(float f) { return __float_as_uint(f); }

__device__ __forceinline__ void cp16(uint32_t dst, const void* src) {
    asm volatile("cp.async.ca.shared.global [%0], [%1], 16;" :: "r"(dst), "l"(src));
}
__device__ __forceinline__ void cp4(uint32_t dst, const void* src) {
    asm volatile("cp.async.ca.shared.global [%0], [%1], 4;" :: "r"(dst), "l"(src));
}
#define CP_COMMIT() asm volatile("cp.async.commit_group;" ::: "memory")
#define CP_WAIT1()  asm volatile("cp.async.wait_group 1;" ::: "memory")
#define CP_WAIT0()  asm volatile("cp.async.wait_group 0;" ::: "memory")

// ============================================================================
// Kernel 1: ext @ [W_off|W_attn]  (M=128/block, N=192, K=128)
// Mixed precision: offset cols (0..127) tf32 3-pass (position-critical,
// R6 measured 1.02e-3 with 2-pass); attn cols (128..191) single-pass rna
// (softmax weights tolerate ~1e-4). Balanced remap: every warp owns
// 64 offset cols + 32 attn cols (j<8 = offsets, j>=8 = attn).
// ============================================================================
#define K1_ABUF (32*LDA136)              // 4352 floats
#define K1_BBUF (32*LDB200)              // 6400 floats
#define K1_STG  (K1_ABUF + K1_BBUF)      // 10752 floats per buffer

__global__ __launch_bounds__(256, 2) void k1_offattn(
    const float* __restrict__ ext, const float* __restrict__ flow,
    const float* __restrict__ W_off, const float* __restrict__ b_off,
    const float* __restrict__ W_attn, const float* __restrict__ b_attn)
{
    extern __shared__ float sm[];
    const int tid  = threadIdx.x;
    const int lane = tid & 31;
    const int warp = tid >> 5;
    const int mw   = warp & 3;
    const int nw   = warp >> 2;
    const int g    = lane >> 2;
    const int tq   = lane & 3;
    const int row0 = blockIdx.x * 128;
    const int b    = row0 / HWQ;
    const int q0   = row0 % HWQ;
    const uint32_t smb = (uint32_t)__cvta_generic_to_shared(sm);

    float acc[2][12][4];
#pragma unroll
    for (int t = 0; t < 2; ++t)
#pragma unroll
        for (int j = 0; j < 12; ++j)
#pragma unroll
            for (int v = 0; v < 4; ++v) acc[t][j][v] = 0.f;

    auto stage = [&](int kc, int buf) {
        uint32_t ab = smb + (uint32_t)(buf*K1_STG)*4u;
        const float* srcA = ext + ((size_t)b*CH + kc*32)*HWQ + q0;
#pragma unroll
        for (int it = 0; it < 4; ++it) {
            int e = tid + it*256;              // < 1024 chunks of 16B
            int k = e >> 5, c4 = e & 31;
            cp16(ab + (uint32_t)(k*LDA136 + c4*4)*4u, srcA + (size_t)k*HWQ + c4*4);
        }
        uint32_t bb = smb + (uint32_t)(buf*K1_STG + K1_ABUF)*4u;
#pragma unroll
        for (int it = 0; it < 6; ++it) {
            int e = tid + it*256;              // < 1536
            int k = e / 48, f4 = e % 48;
            const float* srcp = (f4 < 32)
                ? W_off  + (size_t)(kc*32 + k)*NOFF + f4*4
                : W_attn + (size_t)(kc*32 + k)*NATT + (f4-32)*4;
            cp16(bb + (uint32_t)(k*LDB200 + f4*4)*4u, srcp);
        }
    };

    stage(0, 0); CP_COMMIT();
    for (int kc = 0; kc < 4; ++kc) {
        if (kc < 3) { stage(kc+1, (kc+1)&1); CP_COMMIT(); CP_WAIT1(); }
        else CP_WAIT0();
        __syncthreads();
        const float* As = sm + (kc&1)*K1_STG;
        const float* Bs = As + K1_ABUF;

#pragma unroll
        for (int k8 = 0; k8 < 4; ++k8) {
            const int kr = k8*8 + tq;
            uint32_t ah[2][4], al[2][4], av[2][4];
#pragma unroll
            for (int t = 0; t < 2; ++t) {
                int m = mw*32 + t*16 + g;
                float r0 = As[kr*LDA136 + m];
                float r1 = As[kr*LDA136 + m + 8];
                float r2 = As[(kr+4)*LDA136 + m];
                float r3 = As[(kr+4)*LDA136 + m + 8];
                float h, l;
                split2(r0, h, l); ah[t][0]=fb(h); al[t][0]=fb(l);
                split2(r1, h, l); ah[t][1]=fb(h); al[t][1]=fb(l);
                split2(r2, h, l); ah[t][2]=fb(h); al[t][2]=fb(l);
                split2(r3, h, l); ah[t][3]=fb(h); al[t][3]=fb(l);
                av[t][0]=fbrna(r0); av[t][1]=fbrna(r1);
                av[t][2]=fbrna(r2); av[t][3]=fbrna(r3);
            }
            // ---- offset columns: 3-pass exact ----
#pragma unroll
            for (int j = 0; j < 8; ++j) {
                int n = nw*64 + j*8 + g;           // cols 0..127
                float bh0, bl0, bh1, bl1;
                split2(Bs[kr*LDB200 + n], bh0, bl0);
                split2(Bs[(kr+4)*LDB200 + n], bh1, bl1);
#pragma unroll
                for (int t = 0; t < 2; ++t) {
                    mma_tf32(acc[t][j], ah[t][0],ah[t][1],ah[t][2],ah[t][3], fb(bh0),fb(bh1));
                    mma_tf32(acc[t][j], al[t][0],al[t][1],al[t][2],al[t][3], fb(bh0),fb(bh1));
                    mma_tf32(acc[t][j], ah[t][0],ah[t][1],ah[t][2],ah[t][3], fb(bl0),fb(bl1));
                }
            }
            // ---- attn columns: single-pass rna ----
#pragma unroll
            for (int j = 8; j < 12; ++j) {
                int n = NOFF + nw*32 + (j-8)*8 + g; // cols 128..191
                uint32_t b0 = fbrna(Bs[kr*LDB200 + n]);
                uint32_t b1 = fbrna(Bs[(kr+4)*LDB200 + n]);
#pragma unroll
                for (int t = 0; t < 2; ++t)
                    mma_tf32(acc[t][j], av[t][0],av[t][1],av[t][2],av[t][3], b0,b1);
            }
        }
        if (kc < 3) __syncthreads();
    }

    // ---- epilogue ----
    int   qrow[4]; float fxv[4], fyv[4]; float wiv[4], hiv[4];
#pragma unroll
    for (int t = 0; t < 2; ++t)
#pragma unroll
        for (int rr = 0; rr < 2; ++rr) {
            int r  = mw*32 + t*16 + g + rr*8;
            int qq = q0 + r;
            int ri = t*2 + rr;
            qrow[ri] = qq;
            fxv[ri] = __ldg(&flow[(size_t)b*2*HWQ + qq]);
            fyv[ri] = __ldg(&flow[(size_t)b*2*HWQ + HWQ + qq]);
            wiv[ri] = (float)(qq & (WW-1));
            hiv[ri] = (float)((qq >> 7) & (HH-1));
        }

    // offset j's -> loc
#pragma unroll
    for (int j = 0; j < 8; ++j) {
        int c = nw*64 + j*8 + 2*tq;               // 0..127, even
        int n = c >> 1;
        float b0v = __ldg(&b_off[c]), b1v = __ldg(&b_off[c+1]);
#pragma unroll
        for (int t = 0; t < 2; ++t)
#pragma unroll
            for (int rr = 0; rr < 2; ++rr) {
                int ri = t*2 + rr;
                float ox = MAXRES * tanhf(acc[t][j][rr*2]   + b0v);
                float oy = MAXRES * tanhf(acc[t][j][rr*2+1] + b1v);
                float lx = (wiv[ri] + 0.5f + fxv[ri] + ox) * (1.f/WW);
                float ly = (hiv[ri] + 0.5f + fyv[ri] + oy) * (1.f/HH);
                d_loc[((size_t)b*HWQ + qrow[ri])*NATT + n] = make_float2(lx, ly);
            }
    }
    // attn j's -> softmax (quad tq 0..3 covers one 8-point head)
#pragma unroll
    for (int j = 8; j < 12; ++j) {
        int ca = nw*32 + (j-8)*8 + 2*tq;          // 0..63, even
        float ba0 = __ldg(&b_attn[ca]), ba1 = __ldg(&b_attn[ca+1]);
#pragma unroll
        for (int t = 0; t < 2; ++t)
#pragma unroll
            for (int rr = 0; rr < 2; ++rr) {
                float v0 = acc[t][j][rr*2]   + ba0;
                float v1 = acc[t][j][rr*2+1] + ba1;
                float mx = fmaxf(v0, v1);
                mx = fmaxf(mx, __shfl_xor_sync(0xffffffffu, mx, 1));
                mx = fmaxf(mx, __shfl_xor_sync(0xffffffffu, mx, 2));
                float e0 = __expf(v0 - mx), e1 = __expf(v1 - mx);
                float s = e0 + e1;
                s += __shfl_xor_sync(0xffffffffu, s, 1);
                s += __shfl_xor_sync(0xffffffffu, s, 2);
                float inv = 1.f / s;
                *(float2*)&d_attn[((size_t)b*HWQ + qrow[t*2+rr])*NATT + ca] =
                    make_float2(e0*inv, e1*inv);
            }
    }
}

// ============================================================================
// Kernel 2: val = nbr @ W_val + b_val  (N=128), SINGLE-pass tf32 (A+B rna).
// Output fp16-quantized -> tf32 error below noise floor. fp16 output.
// ============================================================================
#define KV_ABUF (32*LDA136)
#define KV_BBUF (32*LDB136)
#define KV_STG  (KV_ABUF + KV_BBUF)      // 8704 floats

__global__ __launch_bounds__(256, 2) void k_val(
    const float* __restrict__ nbr,
    const float* __restrict__ W_val, const float* __restrict__ b_val)
{
    extern __shared__ float sm[];
    const int tid  = threadIdx.x;
    const int lane = tid & 31;
    const int warp = tid >> 5;
    const int mw   = warp & 3;
    const int nw   = warp >> 2;
    const int g    = lane >> 2;
    const int tq   = lane & 3;
    const int row0 = blockIdx.x * 128;
    const int b    = row0 / HWQ;
    const int q0   = row0 % HWQ;
    const uint32_t smb = (uint32_t)__cvta_generic_to_shared(sm);

    float acc[2][8][4];
#pragma unroll
    for (int t = 0; t < 2; ++t)
#pragma unroll
        for (int j = 0; j < 8; ++j)
#pragma unroll
            for (int v = 0; v < 4; ++v) acc[t][j][v] = 0.f;

    auto stage = [&](int kc, int buf) {
        uint32_t ab = smb + (uint32_t)(buf*KV_STG)*4u;
        const float* srcA = nbr + ((size_t)b*CH + kc*32)*HWQ + q0;
#pragma unroll
        for (int it = 0; it < 4; ++it) {
            int e = tid + it*256;
            int k = e >> 5, c4 = e & 31;
            cp16(ab + (uint32_t)(k*LDA136 + c4*4)*4u, srcA + (size_t)k*HWQ + c4*4);
        }
        uint32_t bb = smb + (uint32_t)(buf*KV_STG + KV_ABUF)*4u;
#pragma unroll
        for (int it = 0; it < 4; ++it) {
            int e = tid + it*256;
            int k = e >> 5, c4 = e & 31;
            cp16(bb + (uint32_t)(k*LDB136 + c4*4)*4u,
                 W_val + (size_t)(kc*32 + k)*CH + c4*4);
        }
    };

    stage(0, 0); CP_COMMIT();
    for (int kc = 0; kc < 4; ++kc) {
        if (kc < 3) { stage(kc+1, (kc+1)&1); CP_COMMIT(); CP_WAIT1(); }
        else CP_WAIT0();
        __syncthreads();
        const float* As = sm + (kc&1)*KV_STG;
        const float* Bs = As + KV_ABUF;

#pragma unroll
        for (int k8 = 0; k8 < 4; ++k8) {
            const int kr = k8*8 + tq;
            uint32_t av[2][4];
#pragma unroll
            for (int t = 0; t < 2; ++t) {
                int m = mw*32 + t*16 + g;
                av[t][0] = fbrna(As[kr*LDA136 + m]);
                av[t][1] = fbrna(As[kr*LDA136 + m + 8]);
                av[t][2] = fbrna(As[(kr+4)*LDA136 + m]);
                av[t][3] = fbrna(As[(kr+4)*LDA136 + m + 8]);
            }
#pragma unroll
            for (int j = 0; j < 8; ++j) {
                int n = nw*64 + j*8 + g;
                uint32_t b0 = fbrna(Bs[kr*LDB136 + n]);
                uint32_t b1 = fbrna(Bs[(kr+4)*LDB136 + n]);
#pragma unroll
                for (int t = 0; t < 2; ++t)
                    mma_tf32(acc[t][j], av[t][0],av[t][1],av[t][2],av[t][3], b0,b1);
            }
        }
        if (kc < 3) __syncthreads();
    }

#pragma unroll
    for (int j = 0; j < 8; ++j) {
        int c = nw*64 + j*8 + 2*tq;
        float b0v = __ldg(&b_val[c]), b1v = __ldg(&b_val[c+1]);
#pragma unroll
        for (int t = 0; t < 2; ++t)
#pragma unroll
            for (int rr = 0; rr < 2; ++rr) {
                int r = row0 + mw*32 + t*16 + g + rr*8;
                __half2 hv = __floats2half2_rn(acc[t][j][rr*2] + b0v,
                                               acc[t][j][rr*2+1] + b1v);
                *(__half2*)&d_val_h[(size_t)r*CH + c] = hv;
            }
    }
}

// ============================================================================
// Kernel 3: bilinear gather (fp16 values) + attention aggregation
// ============================================================================
__device__ __forceinline__ void gacc(float w, const __half* p, float* acc) {
    uint4 gg = __ldg((const uint4*)p);
    float2 f;
    f = __half22float2(*(__half2*)&gg.x); acc[0]=fmaf(w,f.x,acc[0]); acc[1]=fmaf(w,f.y,acc[1]);
    f = __half22float2(*(((__half2*)&gg.x)+1)); acc[2]=fmaf(w,f.x,acc[2]); acc[3]=fmaf(w,f.y,acc[3]);
    f = __half22float2(*(__half2*)&gg.z); acc[4]=fmaf(w,f.x,acc[4]); acc[5]=fmaf(w,f.y,acc[5]);
    f = __half22float2(*(((__half2*)&gg.z)+1)); acc[6]=fmaf(w,f.x,acc[6]); acc[7]=fmaf(w,f.y,acc[7]);
}

__global__ __launch_bounds__(256) void k_gather()
{
    __shared__ float2 loc_s[16][NATT];
    __shared__ float  attn_s[16][NATT];
    const int tx = threadIdx.x;
    const size_t base = (size_t)blockIdx.x * 16;

    for (int i = tx; i < 1024; i += 256) {
        int tq = i >> 6, n = i & 63;
        loc_s[tq][n]  = d_loc [(base + tq)*NATT + n];
        attn_s[tq][n] = d_attn[(base + tq)*NATT + n];
    }
    __syncthreads();

    const int tq = tx >> 4;
    const int c2 = tx & 15;
    const int h  = c2 >> 1;
    const size_t row = base + tq;
    const int b  = (int)(row >> 14);
    const __half* vb = d_val_h + (size_t)b * HWQ * CH + c2*8;

    float acc[8];
#pragma unroll
    for (int i = 0; i < 8; ++i) acc[i] = 0.f;

#pragma unroll
    for (int p = 0; p < NPNT; ++p) {
        int n = h*NPNT + p;
        float2 l = loc_s[tq][n];
        float  a = attn_s[tq][n];
        float x = l.x * (float)WW - 0.5f;
        float y = l.y * (float)HH - 0.5f;
        float x0f = floorf(x), y0f = floorf(y);
        float wx = x - x0f,    wy = y - y0f;
        int x0 = (int)x0f, y0 = (int)y0f;
        int x1 = x0 + 1,   y1 = y0 + 1;
        bool xv0 = (x0 >= 0) & (x0 < WW);
        bool xv1 = (x1 >= 0) & (x1 < WW);
        bool yv0 = (y0 >= 0) & (y0 < HH);
        bool yv1 = (y1 >= 0) & (y1 < HH);
        float w00 = (1.f-wx)*(1.f-wy) * a;
        float w10 = wx*(1.f-wy) * a;
        float w01 = (1.f-wx)*wy * a;
        float w11 = wx*wy * a;
        if (xv0 & yv0) gacc(w00, vb + (size_t)(y0*WW + x0)*CH, acc);
        if (xv1 & yv0) gacc(w10, vb + (size_t)(y0*WW + x1)*CH, acc);
        if (xv0 & yv1) gacc(w01, vb + (size_t)(y1*WW + x0)*CH, acc);
        if (xv1 & yv1) gacc(w11, vb + (size_t)(y1*WW + x1)*CH, acc);
    }
    float* dst = d_agg + row*CH + c2*8;
    *(float4*)dst     = make_float4(acc[0], acc[1], acc[2], acc[3]);
    *(float4*)(dst+4) = make_float4(acc[4], acc[5], acc[6], acc[7]);
}

// ============================================================================
// Kernel 4: out = agg @ W_out + b_out (N=128), SINGLE-pass tf32 (A+B rna).
// ============================================================================
#define KO_ABUF (32*LDA133)              // 4256 floats
#define KO_BBUF (32*LDB136)              // 4352 floats
#define KO_STG  (KO_ABUF + KO_BBUF)      // 8608 floats

__global__ __launch_bounds__(256, 2) void k_out(
    const float* __restrict__ W_out, const float* __restrict__ b_out,
    float* __restrict__ out)
{
    extern __shared__ float sm[];
    const int tid  = threadIdx.x;
    const int lane = tid & 31;
    const int warp = tid >> 5;
    const int mw   = warp & 3;
    const int nw   = warp >> 2;
    const int g    = lane >> 2;
    const int tq   = lane & 3;
    const int row0 = blockIdx.x * 128;
    const int b    = row0 / HWQ;
    const int q0   = row0 % HWQ;
    const uint32_t smb = (uint32_t)__cvta_generic_to_shared(sm);

    float acc[2][8][4];
#pragma unroll
    for (int t = 0; t < 2; ++t)
#pragma unroll
        for (int j = 0; j < 8; ++j)
#pragma unroll
            for (int v = 0; v < 4; ++v) acc[t][j][v] = 0.f;

    auto stage = [&](int kc, int buf) {
        uint32_t ab = smb + (uint32_t)(buf*KO_STG)*4u;
        const float* srcA = d_agg + (size_t)row0*CH + kc*32;
#pragma unroll
        for (int it = 0; it < 16; ++it) {
            int e = tid + it*256;              // 4096 elements
            int m = e >> 5, k = e & 31;
            cp4(ab + (uint32_t)(k*LDA133 + m)*4u, srcA + (size_t)m*CH + k);
        }
        uint32_t bb = smb + (uint32_t)(buf*KO_STG + KO_ABUF)*4u;
#pragma unroll
        for (int it = 0; it < 4; ++it) {
            int e = tid + it*256;
            int k = e >> 5, c4 = e & 31;
            cp16(bb + (uint32_t)(k*LDB136 + c4*4)*4u,
                 W_out + (size_t)(kc*32 + k)*CH + c4*4);
        }
    };

    stage(0, 0); CP_COMMIT();
    for (int kc = 0; kc < 4; ++kc) {
        if (kc < 3) { stage(kc+1, (kc+1)&1); CP_COMMIT(); CP_WAIT1(); }
        else CP_WAIT0();
        __syncthreads();
        const float* As = sm + (kc&1)*KO_STG;
        const float* Bs = As + KO_ABUF;

#pragma unroll
        for (int k8 = 0; k8 < 4; ++k8) {
            const int kr = k8*8 + tq;
            uint32_t av[2][4];
#pragma unroll
            for (int t = 0; t < 2; ++t) {
                int m = mw*32 + t*16 + g;
                av[t][0] = fbrna(As[kr*LDA133 + m]);
                av[t][1] = fbrna(As[kr*LDA133 + m + 8]);
                av[t][2] = fbrna(As[(kr+4)*LDA133 + m]);
                av[t][3] = fbrna(As[(kr+4)*LDA133 + m + 8]);
            }
#pragma unroll
            for (int j = 0; j < 8; ++j) {
                int n = nw*64 + j*8 + g;
                uint32_t b0 = fbrna(Bs[kr*LDB136 + n]);
                uint32_t b1 = fbrna(Bs[(kr+4)*LDB136 + n]);
#pragma unroll
                for (int t = 0; t < 2; ++t)
                    mma_tf32(acc[t][j], av[t][0],av[t][1],av[t][2],av[t][3], b0,b1);
            }
        }
        __syncthreads();
    }

    // stage (acc + bias) into buf[m][129], then coalesced transposed store
    float* buf = sm;                       // reuse; 128*129 = 16512 floats
#pragma unroll
    for (int j = 0; j < 8; ++j) {
        int c = nw*64 + j*8 + 2*tq;
        float b0v = __ldg(&b_out[c]), b1v = __ldg(&b_out[c+1]);
#pragma unroll
        for (int t = 0; t < 2; ++t)
#pragma unroll
            for (int rr = 0; rr < 2; ++rr) {
                int m = mw*32 + t*16 + g + rr*8;
                buf[m*129 + c]     = acc[t][j][rr*2]   + b0v;
                buf[m*129 + c + 1] = acc[t][j][rr*2+1] + b1v;
            }
    }
    __syncthreads();
    for (int idx = tid; idx < 128*128; idx += 256) {
        int m = idx & 127, n = idx >> 7;
        out[(size_t)b*CH*HWQ + (size_t)n*HWQ + q0 + m] = buf[m*129 + n];
    }
}

// ============================================================================
extern "C" void kernel_launch(void* const* d_in, const int* in_sizes, int n_in,
                              void* d_out, int out_size)
{
    const float* nbr    = (const float*)d_in[0];
    const float* ext    = (const float*)d_in[1];
    const float* flow   = (const float*)d_in[2];
    const float* W_off  = (const float*)d_in[3];
    const float* b_off  = (const float*)d_in[4];
    const float* W_attn = (const float*)d_in[5];
    const float* b_attn = (const float*)d_in[6];
    const float* W_val  = (const float*)d_in[7];
    const float* b_val  = (const float*)d_in[8];
    const float* W_out  = (const float*)d_in[9];
    const float* b_out  = (const float*)d_in[10];
    float* out = (float*)d_out;

    const int SM_K1 = 2*K1_STG*4;        // 86016 B  (x2 CTAs = 172KB < 228KB)
    const int SM_KV = 2*KV_STG*4;        // 69632 B
    const int SM_KO = 2*KO_STG*4;        // 68864 B (>= 66048 epilogue buf)

    cudaFuncSetAttribute(k1_offattn, cudaFuncAttributeMaxDynamicSharedMemorySize, SM_K1);
    cudaFuncSetAttribute(k_val,      cudaFuncAttributeMaxDynamicSharedMemorySize, SM_KV);
    cudaFuncSetAttribute(k_out,      cudaFuncAttributeMaxDynamicSharedMemorySize, SM_KO);

    const int nblk = BATCH * HWQ / 128;   // 512

    k1_offattn<<<nblk, 256, SM_K1>>>(ext, flow, W_off, b_off, W_attn, b_attn);
    k_val     <<<nblk, 256, SM_KV>>>(nbr, W_val, b_val);
    k_gather  <<<BATCH * HWQ / 16, 256>>>();
    k_out     <<<nblk, 256, SM_KO>>>(W_out, b_out, out);
}

// round 14
// speedup vs baseline: 1.5430x; 1.0838x over previous
#include <cuda_runtime.h>
#include <cuda_fp16.h>
#include <math.h>
#include <stdint.h>

#define BATCH 4
#define CH    128
#define HH    128
#define WW    128
#define HWQ   16384
#define NHEAD 8
#define NPNT  8
#define NOFF  128
#define NATT  64
#define MAXRES 10.0f

// k_val/k_out strides (unchanged from R12)
#define LDA136 136
#define LDB136 136
#define LDA133 133
// k1 strides: mod 32 == 4 (A, k-pair loads: bank 8tq+g) / == 8 (B pairs)
#define K1_LDA 132
#define K1_LDB 200

// ---- scratch ----
__device__ __half    d_val_h[(size_t)BATCH * HWQ * CH];
__device__ float     d_agg [(size_t)BATCH * HWQ * CH];
__device__ float2    d_loc [(size_t)BATCH * HWQ * NATT];
__device__ float     d_attn[(size_t)BATCH * HWQ * NATT];
__device__ uint32_t  d_PBH[64 * 192];   // pre-split B hi (bf16x2 per k-pair)
__device__ uint32_t  d_PBL[64 * 192];   // pre-split B lo

// ============================================================================
// helpers
// ============================================================================
__device__ __forceinline__ void mma_tf32(float* c, uint32_t a0, uint32_t a1,
                                         uint32_t a2, uint32_t a3,
                                         uint32_t b0, uint32_t b1) {
    asm volatile(
        "mma.sync.aligned.m16n8k8.row.col.f32.tf32.tf32.f32 "
        "{%0,%1,%2,%3},{%4,%5,%6,%7},{%8,%9},{%0,%1,%2,%3};"
        : "+f"(c[0]), "+f"(c[1]), "+f"(c[2]), "+f"(c[3])
        : "r"(a0), "r"(a1), "r"(a2), "r"(a3), "r"(b0), "r"(b1));
}
__device__ __forceinline__ void mma_bf16(float* c, const uint32_t* a,
                                         uint32_t b0, uint32_t b1) {
    asm volatile(
        "mma.sync.aligned.m16n8k16.row.col.f32.bf16.bf16.f32 "
        "{%0,%1,%2,%3},{%4,%5,%6,%7},{%8,%9},{%0,%1,%2,%3};"
        : "+f"(c[0]), "+f"(c[1]), "+f"(c[2]), "+f"(c[3])
        : "r"(a[0]), "r"(a[1]), "r"(a[2]), "r"(a[3]), "r"(b0), "r"(b1));
}
__device__ __forceinline__ uint32_t fbrna(float f) {
    uint32_t r;
    asm("cvt.rna.tf32.f32 %0, %1;" : "=r"(r) : "f"(f));
    return r;
}
__device__ __forceinline__ uint32_t bf16x2(float hi, float lo) {
    uint32_t r;
    asm("cvt.rn.bf16x2.f32 %0, %1, %2;" : "=r"(r) : "f"(hi), "f"(lo));
    return r;
}
__device__ __forceinline__ void cp16(uint32_t dst, const void* src) {
    asm volatile("cp.async.ca.shared.global [%0], [%1], 16;" :: "r"(dst), "l"(src));
}
__device__ __forceinline__ void cp4(uint32_t dst, const void* src) {
    asm volatile("cp.async.ca.shared.global [%0], [%1], 4;" :: "r"(dst), "l"(src));
}
#define CP_COMMIT() asm volatile("cp.async.commit_group;" ::: "memory")
#define CP_WAIT1()  asm volatile("cp.async.wait_group 1;" ::: "memory")
#define CP_WAIT0()  asm volatile("cp.async.wait_group 0;" ::: "memory")

// ============================================================================
// prep_B: split [W_off|W_attn] into packed bf16x2 hi/lo per k-pair.
// hi = round-to-nearest bf16 (unbiased residual), lo = bf16(v - hi).
// 48 blocks x 256 = 12288 = 64 pairs * 192 cols.
// ============================================================================
__global__ void prep_B(const float* __restrict__ W_off,
                       const float* __restrict__ W_attn)
{
    int idx = blockIdx.x * 256 + threadIdx.x;   // < 12288
    int p = idx / 192, n = idx % 192;
    float v0, v1;
    if (n < NOFF) {
        v0 = W_off[(size_t)(2*p)   * NOFF + n];
        v1 = W_off[(size_t)(2*p+1) * NOFF + n];
    } else {
        v0 = W_attn[(size_t)(2*p)   * NATT + (n - NOFF)];
        v1 = W_attn[(size_t)(2*p+1) * NATT + (n - NOFF)];
    }
    uint32_t h = bf16x2(v1, v0);
    float h0 = __uint_as_float((h & 0xFFFFu) << 16);
    float h1 = __uint_as_float(h & 0xFFFF0000u);
    d_PBH[idx] = h;
    d_PBL[idx] = bf16x2(v1 - h1, v0 - h0);
}

// ============================================================================
// Kernel 1: ext @ [W_off|W_attn]  (M=128/block, N=192, K=128)
// bf16 m16n8k16 3-term (AhBh + AlBh + AhBl), A split in registers
// (truncation hi + bf16 lo; unbiased combined with rn-B), B pre-split.
// ~1e-5 per-element error — 14x tighter than the R6-failed tf32-rna.
// ============================================================================
#define K1_ABUF (32*K1_LDA)              // 4224 u32 (raw fp32 A)
#define K1_BBUF (16*K1_LDB)              // 3200 u32 per array
#define K1_STG  (K1_ABUF + 2*K1_BBUF)    // 10624 u32 per buffer

__global__ __launch_bounds__(256, 2) void k1_offattn(
    const float* __restrict__ ext, const float* __restrict__ flow,
    const float* __restrict__ b_off, const float* __restrict__ b_attn)
{
    extern __shared__ float sm[];
    const int tid  = threadIdx.x;
    const int lane = tid & 31;
    const int warp = tid >> 5;
    const int mw   = warp & 3;
    const int nw   = warp >> 2;
    const int g    = lane >> 2;
    const int tq   = lane & 3;
    const int row0 = blockIdx.x * 128;
    const int b    = row0 / HWQ;
    const int q0   = row0 % HWQ;
    const uint32_t smb = (uint32_t)__cvta_generic_to_shared(sm);

    float acc[2][12][4];
#pragma unroll
    for (int t = 0; t < 2; ++t)
#pragma unroll
        for (int j = 0; j < 12; ++j)
#pragma unroll
            for (int v = 0; v < 4; ++v) acc[t][j][v] = 0.f;

    auto stage = [&](int kc, int buf) {
        uint32_t ab = smb + (uint32_t)(buf*K1_STG)*4u;
        const float* srcA = ext + ((size_t)b*CH + kc*32)*HWQ + q0;
#pragma unroll
        for (int it = 0; it < 4; ++it) {
            int e = tid + it*256;              // < 1024 chunks of 16B
            int k = e >> 5, c4 = e & 31;
            cp16(ab + (uint32_t)(k*K1_LDA + c4*4)*4u, srcA + (size_t)k*HWQ + c4*4);
        }
        uint32_t bb = smb + (uint32_t)(buf*K1_STG + K1_ABUF)*4u;
#pragma unroll
        for (int it = 0; it < 6; ++it) {
            int e = tid + it*256;              // < 1536
            int arr = e >> 9 >= 1 ? (e >= 768 ? 1 : 0) : 0;   // e>=768 -> lo
            arr = (e >= 768);
            int e2 = e - arr*768;
            int r = e2 / 48, ch = e2 % 48;
            const uint32_t* src = (arr ? d_PBL : d_PBH) + (size_t)(kc*16 + r)*192 + ch*4;
            cp16(bb + (uint32_t)(arr*K1_BBUF + r*K1_LDB + ch*4)*4u, src);
        }
    };

    stage(0, 0); CP_COMMIT();
    for (int kc = 0; kc < 4; ++kc) {
        if (kc < 3) { stage(kc+1, (kc+1)&1); CP_COMMIT(); CP_WAIT1(); }
        else CP_WAIT0();
        __syncthreads();
        const float*    As  = sm + (kc&1)*K1_STG;
        const uint32_t* BHs = (const uint32_t*)(As + K1_ABUF);
        const uint32_t* BLs = BHs + K1_BBUF;

#pragma unroll
        for (int kh = 0; kh < 2; ++kh) {       // two k16 chunks per K=32
            const int ka = kh*16 + 2*tq;       // A k-pair base
            const int lp = kh*8 + tq;          // B pair row
            uint32_t ah[2][4], al[2][4];
#pragma unroll
            for (int t = 0; t < 2; ++t) {
                int m = mw*32 + t*16 + g;
#pragma unroll
                for (int f = 0; f < 4; ++f) {
                    int kk = ka + (f >> 1)*8;          // f=0,1: ka; f=2,3: ka+8
                    int mm = m + (f & 1)*8;            // f even: m; odd: m+8
                    float v0 = As[kk*K1_LDA + mm];
                    float v1 = As[(kk+1)*K1_LDA + mm];
                    uint32_t u0 = __float_as_uint(v0), u1 = __float_as_uint(v1);
                    ah[t][f] = __byte_perm(u0, u1, 0x7632);        // trunc hi pair
                    float h0 = __uint_as_float(u0 & 0xFFFF0000u);
                    float h1 = __uint_as_float(u1 & 0xFFFF0000u);
                    al[t][f] = bf16x2(v1 - h1, v0 - h0);           // lo pair
                }
            }
#pragma unroll
            for (int j = 0; j < 12; ++j) {
                int n = (j < 8) ? (nw*64 + j*8 + g)
                                : (NOFF + nw*32 + (j-8)*8 + g);
                uint32_t bh0 = BHs[lp*K1_LDB + n];
                uint32_t bh1 = BHs[(lp+4)*K1_LDB + n];
                uint32_t bl0 = BLs[lp*K1_LDB + n];
                uint32_t bl1 = BLs[(lp+4)*K1_LDB + n];
#pragma unroll
                for (int t = 0; t < 2; ++t) {
                    mma_bf16(acc[t][j], ah[t], bh0, bh1);
                    mma_bf16(acc[t][j], al[t], bh0, bh1);
                    mma_bf16(acc[t][j], ah[t], bl0, bl1);
                }
            }
        }
        if (kc < 3) __syncthreads();
    }

    // ---- epilogue ----
    int   qrow[4]; float fxv[4], fyv[4]; float wiv[4], hiv[4];
#pragma unroll
    for (int t = 0; t < 2; ++t)
#pragma unroll
        for (int rr = 0; rr < 2; ++rr) {
            int r  = mw*32 + t*16 + g + rr*8;
            int qq = q0 + r;
            int ri = t*2 + rr;
            qrow[ri] = qq;
            fxv[ri] = __ldg(&flow[(size_t)b*2*HWQ + qq]);
            fyv[ri] = __ldg(&flow[(size_t)b*2*HWQ + HWQ + qq]);
            wiv[ri] = (float)(qq & (WW-1));
            hiv[ri] = (float)((qq >> 7) & (HH-1));
        }

    // offset j's -> loc
#pragma unroll
    for (int j = 0; j < 8; ++j) {
        int c = nw*64 + j*8 + 2*tq;               // 0..127, even
        int n = c >> 1;
        float b0v = __ldg(&b_off[c]), b1v = __ldg(&b_off[c+1]);
#pragma unroll
        for (int t = 0; t < 2; ++t)
#pragma unroll
            for (int rr = 0; rr < 2; ++rr) {
                int ri = t*2 + rr;
                float ox = MAXRES * tanhf(acc[t][j][rr*2]   + b0v);
                float oy = MAXRES * tanhf(acc[t][j][rr*2+1] + b1v);
                float lx = (wiv[ri] + 0.5f + fxv[ri] + ox) * (1.f/WW);
                float ly = (hiv[ri] + 0.5f + fyv[ri] + oy) * (1.f/HH);
                d_loc[((size_t)b*HWQ + qrow[ri])*NATT + n] = make_float2(lx, ly);
            }
    }
    // attn j's -> softmax
#pragma unroll
    for (int j = 8; j < 12; ++j) {
        int ca = nw*32 + (j-8)*8 + 2*tq;          // 0..63, even
        float ba0 = __ldg(&b_attn[ca]), ba1 = __ldg(&b_attn[ca+1]);
#pragma unroll
        for (int t = 0; t < 2; ++t)
#pragma unroll
            for (int rr = 0; rr < 2; ++rr) {
                float v0 = acc[t][j][rr*2]   + ba0;
                float v1 = acc[t][j][rr*2+1] + ba1;
                float mx = fmaxf(v0, v1);
                mx = fmaxf(mx, __shfl_xor_sync(0xffffffffu, mx, 1));
                mx = fmaxf(mx, __shfl_xor_sync(0xffffffffu, mx, 2));
                float e0 = __expf(v0 - mx), e1 = __expf(v1 - mx);
                float s = e0 + e1;
                s += __shfl_xor_sync(0xffffffffu, s, 1);
                s += __shfl_xor_sync(0xffffffffu, s, 2);
                float inv = 1.f / s;
                *(float2*)&d_attn[((size_t)b*HWQ + qrow[t*2+rr])*NATT + ca] =
                    make_float2(e0*inv, e1*inv);
            }
    }
}

// ============================================================================
// Kernel 2: val = nbr @ W_val + b_val  (N=128), single-pass tf32, fp16 out.
// ============================================================================
#define KV_ABUF (32*LDA136)
#define KV_BBUF (32*LDB136)
#define KV_STG  (KV_ABUF + KV_BBUF)

__global__ __launch_bounds__(256, 2) void k_val(
    const float* __restrict__ nbr,
    const float* __restrict__ W_val, const float* __restrict__ b_val)
{
    extern __shared__ float sm[];
    const int tid  = threadIdx.x;
    const int lane = tid & 31;
    const int warp = tid >> 5;
    const int mw   = warp & 3;
    const int nw   = warp >> 2;
    const int g    = lane >> 2;
    const int tq   = lane & 3;
    const int row0 = blockIdx.x * 128;
    const int b    = row0 / HWQ;
    const int q0   = row0 % HWQ;
    const uint32_t smb = (uint32_t)__cvta_generic_to_shared(sm);

    float acc[2][8][4];
#pragma unroll
    for (int t = 0; t < 2; ++t)
#pragma unroll
        for (int j = 0; j < 8; ++j)
#pragma unroll
            for (int v = 0; v < 4; ++v) acc[t][j][v] = 0.f;

    auto stage = [&](int kc, int buf) {
        uint32_t ab = smb + (uint32_t)(buf*KV_STG)*4u;
        const float* srcA = nbr + ((size_t)b*CH + kc*32)*HWQ + q0;
#pragma unroll
        for (int it = 0; it < 4; ++it) {
            int e = tid + it*256;
            int k = e >> 5, c4 = e & 31;
            cp16(ab + (uint32_t)(k*LDA136 + c4*4)*4u, srcA + (size_t)k*HWQ + c4*4);
        }
        uint32_t bb = smb + (uint32_t)(buf*KV_STG + KV_ABUF)*4u;
#pragma unroll
        for (int it = 0; it < 4; ++it) {
            int e = tid + it*256;
            int k = e >> 5, c4 = e & 31;
            cp16(bb + (uint32_t)(k*LDB136 + c4*4)*4u,
                 W_val + (size_t)(kc*32 + k)*CH + c4*4);
        }
    };

    stage(0, 0); CP_COMMIT();
    for (int kc = 0; kc < 4; ++kc) {
        if (kc < 3) { stage(kc+1, (kc+1)&1); CP_COMMIT(); CP_WAIT1(); }
        else CP_WAIT0();
        __syncthreads();
        const float* As = sm + (kc&1)*KV_STG;
        const float* Bs = As + KV_ABUF;

#pragma unroll
        for (int k8 = 0; k8 < 4; ++k8) {
            const int kr = k8*8 + tq;
            uint32_t av[2][4];
#pragma unroll
            for (int t = 0; t < 2; ++t) {
                int m = mw*32 + t*16 + g;
                av[t][0] = fbrna(As[kr*LDA136 + m]);
                av[t][1] = fbrna(As[kr*LDA136 + m + 8]);
                av[t][2] = fbrna(As[(kr+4)*LDA136 + m]);
                av[t][3] = fbrna(As[(kr+4)*LDA136 + m + 8]);
            }
#pragma unroll
            for (int j = 0; j < 8; ++j) {
                int n = nw*64 + j*8 + g;
                uint32_t b0 = fbrna(Bs[kr*LDB136 + n]);
                uint32_t b1 = fbrna(Bs[(kr+4)*LDB136 + n]);
#pragma unroll
                for (int t = 0; t < 2; ++t)
                    mma_tf32(acc[t][j], av[t][0],av[t][1],av[t][2],av[t][3], b0,b1);
            }
        }
        if (kc < 3) __syncthreads();
    }

#pragma unroll
    for (int j = 0; j < 8; ++j) {
        int c = nw*64 + j*8 + 2*tq;
        float b0v = __ldg(&b_val[c]), b1v = __ldg(&b_val[c+1]);
#pragma unroll
        for (int t = 0; t < 2; ++t)
#pragma unroll
            for (int rr = 0; rr < 2; ++rr) {
                int r = row0 + mw*32 + t*16 + g + rr*8;
                __half2 hv = __floats2half2_rn(acc[t][j][rr*2] + b0v,
                                               acc[t][j][rr*2+1] + b1v);
                *(__half2*)&d_val_h[(size_t)r*CH + c] = hv;
            }
    }
}

// ============================================================================
// Kernel 3: bilinear gather (fp16 values) + attention aggregation
// ============================================================================
__device__ __forceinline__ void gacc(float w, const __half* p, float* acc) {
    uint4 gg = __ldg((const uint4*)p);
    float2 f;
    f = __half22float2(*(__half2*)&gg.x); acc[0]=fmaf(w,f.x,acc[0]); acc[1]=fmaf(w,f.y,acc[1]);
    f = __half22float2(*(((__half2*)&gg.x)+1)); acc[2]=fmaf(w,f.x,acc[2]); acc[3]=fmaf(w,f.y,acc[3]);
    f = __half22float2(*(__half2*)&gg.z); acc[4]=fmaf(w,f.x,acc[4]); acc[5]=fmaf(w,f.y,acc[5]);
    f = __half22float2(*(((__half2*)&gg.z)+1)); acc[6]=fmaf(w,f.x,acc[6]); acc[7]=fmaf(w,f.y,acc[7]);
}

__global__ __launch_bounds__(256) void k_gather()
{
    __shared__ float2 loc_s[16][NATT];
    __shared__ float  attn_s[16][NATT];
    const int tx = threadIdx.x;
    const size_t base = (size_t)blockIdx.x * 16;

    for (int i = tx; i < 1024; i += 256) {
        int tq = i >> 6, n = i & 63;
        loc_s[tq][n]  = d_loc [(base + tq)*NATT + n];
        attn_s[tq][n] = d_attn[(base + tq)*NATT + n];
    }
    __syncthreads();

    const int tq = tx >> 4;
    const int c2 = tx & 15;
    const int h  = c2 >> 1;
    const size_t row = base + tq;
    const int b  = (int)(row >> 14);
    const __half* vb = d_val_h + (size_t)b * HWQ * CH + c2*8;

    float acc[8];
#pragma unroll
    for (int i = 0; i < 8; ++i) acc[i] = 0.f;

#pragma unroll
    for (int p = 0; p < NPNT; ++p) {
        int n = h*NPNT + p;
        float2 l = loc_s[tq][n];
        float  a = attn_s[tq][n];
        float x = l.x * (float)WW - 0.5f;
        float y = l.y * (float)HH - 0.5f;
        float x0f = floorf(x), y0f = floorf(y);
        float wx = x - x0f,    wy = y - y0f;
        int x0 = (int)x0f, y0 = (int)y0f;
        int x1 = x0 + 1,   y1 = y0 + 1;
        bool xv0 = (x0 >= 0) & (x0 < WW);
        bool xv1 = (x1 >= 0) & (x1 < WW);
        bool yv0 = (y0 >= 0) & (y0 < HH);
        bool yv1 = (y1 >= 0) & (y1 < HH);
        float w00 = (1.f-wx)*(1.f-wy) * a;
        float w10 = wx*(1.f-wy) * a;
        float w01 = (1.f-wx)*wy * a;
        float w11 = wx*wy * a;
        if (xv0 & yv0) gacc(w00, vb + (size_t)(y0*WW + x0)*CH, acc);
        if (xv1 & yv0) gacc(w10, vb + (size_t)(y0*WW + x1)*CH, acc);
        if (xv0 & yv1) gacc(w01, vb + (size_t)(y1*WW + x0)*CH, acc);
        if (xv1 & yv1) gacc(w11, vb + (size_t)(y1*WW + x1)*CH, acc);
    }
    float* dst = d_agg + row*CH + c2*8;
    *(float4*)dst     = make_float4(acc[0], acc[1], acc[2], acc[3]);
    *(float4*)(dst+4) = make_float4(acc[4], acc[5], acc[6], acc[7]);
}

// ============================================================================
// Kernel 4: out = agg @ W_out + b_out (N=128), single-pass tf32,
// transposed store.
// ============================================================================
#define KO_ABUF (32*LDA133)
#define KO_BBUF (32*LDB136)
#define KO_STG  (KO_ABUF + KO_BBUF)

__global__ __launch_bounds__(256, 2) void k_out(
    const float* __restrict__ W_out, const float* __restrict__ b_out,
    float* __restrict__ out)
{
    extern __shared__ float sm[];
    const int tid  = threadIdx.x;
    const int lane = tid & 31;
    const int warp = tid >> 5;
    const int mw   = warp & 3;
    const int nw   = warp >> 2;
    const int g    = lane >> 2;
    const int tq   = lane & 3;
    const int row0 = blockIdx.x * 128;
    const int b    = row0 / HWQ;
    const int q0   = row0 % HWQ;
    const uint32_t smb = (uint32_t)__cvta_generic_to_shared(sm);

    float acc[2][8][4];
#pragma unroll
    for (int t = 0; t < 2; ++t)
#pragma unroll
        for (int j = 0; j < 8; ++j)
#pragma unroll
            for (int v = 0; v < 4; ++v) acc[t][j][v] = 0.f;

    auto stage = [&](int kc, int buf) {
        uint32_t ab = smb + (uint32_t)(buf*KO_STG)*4u;
        const float* srcA = d_agg + (size_t)row0*CH + kc*32;
#pragma unroll
        for (int it = 0; it < 16; ++it) {
            int e = tid + it*256;
            int m = e >> 5, k = e & 31;
            cp4(ab + (uint32_t)(k*LDA133 + m)*4u, srcA + (size_t)m*CH + k);
        }
        uint32_t bb = smb + (uint32_t)(buf*KO_STG + KO_ABUF)*4u;
#pragma unroll
        for (int it = 0; it < 4; ++it) {
            int e = tid + it*256;
            int k = e >> 5, c4 = e & 31;
            cp16(bb + (uint32_t)(k*LDB136 + c4*4)*4u,
                 W_out + (size_t)(kc*32 + k)*CH + c4*4);
        }
    };

    stage(0, 0); CP_COMMIT();
    for (int kc = 0; kc < 4; ++kc) {
        if (kc < 3) { stage(kc+1, (kc+1)&1); CP_COMMIT(); CP_WAIT1(); }
        else CP_WAIT0();
        __syncthreads();
        const float* As = sm + (kc&1)*KO_STG;
        const float* Bs = As + KO_ABUF;

#pragma unroll
        for (int k8 = 0; k8 < 4; ++k8) {
            const int kr = k8*8 + tq;
            uint32_t av[2][4];
#pragma unroll
            for (int t = 0; t < 2; ++t) {
                int m = mw*32 + t*16 + g;
                av[t][0] = fbrna(As[kr*LDA133 + m]);
                av[t][1] = fbrna(As[kr*LDA133 + m + 8]);
                av[t][2] = fbrna(As[(kr+4)*LDA133 + m]);
                av[t][3] = fbrna(As[(kr+4)*LDA133 + m + 8]);
            }
#pragma unroll
            for (int j = 0; j < 8; ++j) {
                int n = nw*64 + j*8 + g;
                uint32_t b0 = fbrna(Bs[kr*LDB136 + n]);
                uint32_t b1 = fbrna(Bs[(kr+4)*LDB136 + n]);
#pragma unroll
                for (int t = 0; t < 2; ++t)
                    mma_tf32(acc[t][j], av[t][0],av[t][1],av[t][2],av[t][3], b0,b1);
            }
        }
        __syncthreads();
    }

    float* buf = sm;                       // reuse; 128*129 = 16512 floats
#pragma unroll
    for (int j = 0; j < 8; ++j) {
        int c = nw*64 + j*8 + 2*tq;
        float b0v = __ldg(&b_out[c]), b1v = __ldg(&b_out[c+1]);
#pragma unroll
        for (int t = 0; t < 2; ++t)
#pragma unroll
            for (int rr = 0; rr < 2; ++rr) {
                int m = mw*32 + t*16 + g + rr*8;
                buf[m*129 + c]     = acc[t][j][rr*2]   + b0v;
                buf[m*129 + c + 1] = acc[t][j][rr*2+1] + b1v;
            }
    }
    __syncthreads();
    for (int idx = tid; idx < 128*128; idx += 256) {
        int m = idx & 127, n = idx >> 7;
        out[(size_t)b*CH*HWQ + (size_t)n*HWQ + q0 + m] = buf[m*129 + n];
    }
}

// ============================================================================
extern "C" void kernel_launch(void* const* d_in, const int* in_sizes, int n_in,
                              void* d_out, int out_size)
{
    const float* nbr    = (const float*)d_in[0];
    const float* ext    = (const float*)d_in[1];
    const float* flow   = (const float*)d_in[2];
    const float* W_off  = (const float*)d_in[3];
    const float* b_off  = (const float*)d_in[4];
    const float* W_attn = (const float*)d_in[5];
    const float* b_attn = (const float*)d_in[6];
    const float* W_val  = (const float*)d_in[7];
    const float* b_val  = (const float*)d_in[8];
    const float* W_out  = (const float*)d_in[9];
    const float* b_out  = (const float*)d_in[10];
    float* out = (float*)d_out;

    const int SM_K1 = 2*K1_STG*4;        // 84992 B (x2 CTAs = 170KB < 228KB)
    const int SM_KV = 2*KV_STG*4;
    const int SM_KO = 2*KO_STG*4;        // >= 66048 epilogue buf

    cudaFuncSetAttribute(k1_offattn, cudaFuncAttributeMaxDynamicSharedMemorySize, SM_K1);
    cudaFuncSetAttribute(k_val,      cudaFuncAttributeMaxDynamicSharedMemorySize, SM_KV);
    cudaFuncSetAttribute(k_out,      cudaFuncAttributeMaxDynamicSharedMemorySize, SM_KO);

    const int nblk = BATCH * HWQ / 128;   // 512

    prep_B    <<<48, 256>>>(W_off, W_attn);
    k1_offattn<<<nblk, 256, SM_K1>>>(ext, flow, b_off, b_attn);
    k_val     <<<nblk, 256, SM_KV>>>(nbr, W_val, b_val);
    k_gather  <<<BATCH * HWQ / 16, 256>>>();
    k_out     <<<nblk, 256, SM_KO>>>(W_out, b_out, out);
}